// round 1
// baseline (speedup 1.0000x reference)
#include <cuda_runtime.h>
#include <math.h>

#define N_ 64
#define C_ 512
#define S_ 1024
#define K_ 64

// Scratch (device globals: allocation-free per harness rules)
__device__ float g_invnorm[N_ * S_];        // 256 KB
__device__ float g_a[N_ * K_ * S_];         // 16.8 MB
__device__ float g_asum[N_ * K_];           // 16 KB
__device__ float g_vlad[N_ * K_ * C_];      // 8.4 MB
__device__ float g_nsum[N_];

// ---------------------------------------------------------------------------
// K1: per-pixel inverse L2 norm over channels; also zero accumulators.
// Thread t handles pixel (n, s). Adjacent threads -> adjacent s -> coalesced.
// ---------------------------------------------------------------------------
__global__ void k1_invnorm(const float* __restrict__ x) {
    int idx = blockIdx.x * 256 + threadIdx.x;   // 0 .. N*S-1 (65536)
    int n = idx >> 10;
    int s = idx & (S_ - 1);
    const float* p = x + (size_t)n * C_ * S_ + s;
    float acc = 0.f;
#pragma unroll 8
    for (int c = 0; c < C_; ++c) {
        float v = p[(size_t)c * S_];
        acc += v * v;
    }
    g_invnorm[idx] = 1.f / fmaxf(sqrtf(acc), 1e-12f);

    if (idx < N_ * K_) g_asum[idx] = 0.f;
    if (idx < N_)      g_nsum[idx] = 0.f;
}

// ---------------------------------------------------------------------------
// K2: logits tile (64 x 128) = W(64x512) @ Xn(512 x 128)  then softmax over K.
// grid (8 s-tiles, 64 n), 256 threads. Each thread: 8(k) x 4(s) register tile.
// smem union: [Ws 32x65 | Xs 32x132] overlaid by Ls 64x129 for softmax.
// ---------------------------------------------------------------------------
__global__ void k2_gemm1_softmax(const float* __restrict__ x,
                                 const float* __restrict__ w) {
    __shared__ __align__(16) float sh[8256];           // 33 KB
    float (*Ws)[K_ + 1]  = (float (*)[K_ + 1])sh;      // 32 x 65  = 2080
    float (*Xs)[132]     = (float (*)[132])(sh + 2080); // 32 x 132 = 4224 (16B-aligned rows)
    float (*Ls)[129]     = (float (*)[129])sh;          // 64 x 129 = 8256 (reuse)

    int n  = blockIdx.y;
    int s0 = blockIdx.x * 128;
    int t  = threadIdx.x;
    int tk = t >> 5, ts = t & 31;
    int k0 = tk * 8, sc0 = ts * 4;

    const float* xn  = x + (size_t)n * C_ * S_;
    const float* inv = g_invnorm + n * S_ + s0;

    float acc[8][4];
#pragma unroll
    for (int i = 0; i < 8; ++i)
#pragma unroll
        for (int j = 0; j < 4; ++j) acc[i][j] = 0.f;

    for (int c0 = 0; c0 < C_; c0 += 32) {
        __syncthreads();
        // W tile: W[k][c0+cc] -> Ws[cc][k] (coalesced gmem read; padded STS)
        {
            int cc = t & 31, kk = t >> 5;
#pragma unroll
            for (int j = 0; j < 8; ++j) {
                int k = kk + j * 8;
                Ws[cc][k] = w[k * C_ + c0 + cc];
            }
        }
        // X tile: xn[c0+cc][s0+ss] * invnorm -> Xs[cc][ss] (fully coalesced)
#pragma unroll
        for (int j = 0; j < 16; ++j) {
            int idx = j * 256 + t;
            int cc = idx >> 7, ss = idx & 127;
            Xs[cc][ss] = xn[(size_t)(c0 + cc) * S_ + s0 + ss] * inv[ss];
        }
        __syncthreads();

#pragma unroll 4
        for (int cc = 0; cc < 32; ++cc) {
            float wv[8];
#pragma unroll
            for (int i = 0; i < 8; ++i) wv[i] = Ws[cc][k0 + i];
            float4 xv = *(const float4*)&Xs[cc][sc0];
            float xa0 = xv.x, xa1 = xv.y, xa2 = xv.z, xa3 = xv.w;
#pragma unroll
            for (int i = 0; i < 8; ++i) {
                acc[i][0] += wv[i] * xa0;
                acc[i][1] += wv[i] * xa1;
                acc[i][2] += wv[i] * xa2;
                acc[i][3] += wv[i] * xa3;
            }
        }
    }

    // Stage logits to smem for cross-k softmax
    __syncthreads();
#pragma unroll
    for (int i = 0; i < 8; ++i)
#pragma unroll
        for (int j = 0; j < 4; ++j) Ls[k0 + i][sc0 + j] = acc[i][j];
    __syncthreads();

    if (t < 128) {
        int s = t;
        float m = -1e30f;
#pragma unroll
        for (int k = 0; k < K_; ++k) m = fmaxf(m, Ls[k][s]);
        float sum = 0.f;
#pragma unroll
        for (int k = 0; k < K_; ++k) {
            float e = expf(Ls[k][s] - m);
            Ls[k][s] = e;
            sum += e;
        }
        float r = 1.f / sum;
#pragma unroll
        for (int k = 0; k < K_; ++k) {
            float a = Ls[k][s] * r;
            Ls[k][s] = a;
            g_a[((size_t)n * K_ + k) * S_ + s0 + s] = a;  // coalesced per k
        }
    }
    __syncthreads();
    if (t < K_) {
        float ssum = 0.f;
#pragma unroll
        for (int ss = 0; ss < 128; ++ss) ssum += Ls[t][ss];
        atomicAdd(&g_asum[n * K_ + t], ssum);
    }
}

// ---------------------------------------------------------------------------
// K3: vlad tile (64 x 128) = A(64x1024) @ Xn^T(1024 x 128c-slice).
// grid (4 c-tiles, 64 n), 256 threads, S tiled by 32.
// ---------------------------------------------------------------------------
__global__ void k3_gemm2(const float* __restrict__ x) {
    __shared__ __align__(16) float As[32][K_ + 1];   // [s][k] 8.3 KB
    __shared__ __align__(16) float Xs[32][132];      // [s][c] 16.9 KB

    int n  = blockIdx.y;
    int c0 = blockIdx.x * 128;
    int t  = threadIdx.x;
    int tk = t >> 5, tc = t & 31;
    int k0 = tk * 8, cc0 = tc * 4;

    const float* xn  = x + (size_t)n * C_ * S_;
    const float* an  = g_a + (size_t)n * K_ * S_;
    const float* inv = g_invnorm + n * S_;

    float acc[8][4];
#pragma unroll
    for (int i = 0; i < 8; ++i)
#pragma unroll
        for (int j = 0; j < 4; ++j) acc[i][j] = 0.f;

    for (int s0 = 0; s0 < S_; s0 += 32) {
        __syncthreads();
        // A tile: a[k][s0+ss] -> As[ss][k]
        {
            int ss = t & 31, kk = t >> 5;
#pragma unroll
            for (int j = 0; j < 8; ++j) {
                int k = kk + j * 8;
                As[ss][k] = an[(size_t)k * S_ + s0 + ss];
            }
        }
        // X tile: xn[c0+ci][s0+ss] * invnorm -> Xs[ss][ci]
#pragma unroll
        for (int j = 0; j < 16; ++j) {
            int idx = j * 256 + t;
            int ci = idx >> 5, ss = idx & 31;
            Xs[ss][ci] = xn[(size_t)(c0 + ci) * S_ + s0 + ss] * inv[s0 + ss];
        }
        __syncthreads();

#pragma unroll 4
        for (int ss = 0; ss < 32; ++ss) {
            float av[8];
#pragma unroll
            for (int i = 0; i < 8; ++i) av[i] = As[ss][k0 + i];
            float4 xv = *(const float4*)&Xs[ss][cc0];
            float xa0 = xv.x, xa1 = xv.y, xa2 = xv.z, xa3 = xv.w;
#pragma unroll
            for (int i = 0; i < 8; ++i) {
                acc[i][0] += av[i] * xa0;
                acc[i][1] += av[i] * xa1;
                acc[i][2] += av[i] * xa2;
                acc[i][3] += av[i] * xa3;
            }
        }
    }

#pragma unroll
    for (int i = 0; i < 8; ++i) {
        float4 v = make_float4(acc[i][0], acc[i][1], acc[i][2], acc[i][3]);
        *(float4*)&g_vlad[((size_t)n * K_ + (k0 + i)) * C_ + c0 + cc0] = v;
    }
}

// ---------------------------------------------------------------------------
// K4: per-(n,k) row: subtract asum*centroid, intra-L2-normalize, write out,
// accumulate per-n global sumsq. grid 4096 blocks x 128 threads.
// ---------------------------------------------------------------------------
__global__ void k4_intranorm(const float* __restrict__ centroids,
                             float* __restrict__ out) {
    int nk = blockIdx.x;
    int n = nk >> 6, k = nk & 63;
    int t = threadIdx.x;

    float asum = g_asum[nk];
    float v[4];
    float ss = 0.f;
#pragma unroll
    for (int j = 0; j < 4; ++j) {
        int c = t + j * 128;
        float val = g_vlad[(size_t)nk * C_ + c] - asum * centroids[k * C_ + c];
        v[j] = val;
        ss += val * val;
    }
    // block reduce (4 warps)
#pragma unroll
    for (int o = 16; o; o >>= 1) ss += __shfl_xor_sync(0xffffffffu, ss, o);
    __shared__ float red[4];
    if ((t & 31) == 0) red[t >> 5] = ss;
    __syncthreads();
    float total = red[0] + red[1] + red[2] + red[3];

    float invn = 1.f / fmaxf(sqrtf(total), 1e-12f);
    if (t == 0) atomicAdd(&g_nsum[n], total * invn * invn);

#pragma unroll
    for (int j = 0; j < 4; ++j) {
        int c = t + j * 128;
        out[(size_t)n * (K_ * C_) + k * C_ + c] = v[j] * invn;
    }
}

// ---------------------------------------------------------------------------
// K5: global L2 normalization per n.
// ---------------------------------------------------------------------------
__global__ void k5_globalnorm(float* __restrict__ out) {
    int idx = blockIdx.x * 256 + threadIdx.x;    // 0 .. N*K*C-1
    int n = idx >> 15;                            // / (K_*C_)
    float g = g_nsum[n];
    out[idx] *= 1.f / fmaxf(sqrtf(g), 1e-12f);
}

// ---------------------------------------------------------------------------
extern "C" void kernel_launch(void* const* d_in, const int* in_sizes, int n_in,
                              void* d_out, int out_size) {
    const float* x    = (const float*)d_in[0];   // (64,512,32,32)
    const float* w    = (const float*)d_in[1];   // (64,512)
    const float* cent = (const float*)d_in[2];   // (64,512)
    float* out = (float*)d_out;                  // (64, 64*512)

    k1_invnorm<<<(N_ * S_) / 256, 256>>>(x);
    k2_gemm1_softmax<<<dim3(S_ / 128, N_), 256>>>(x, w);
    k3_gemm2<<<dim3(C_ / 128, N_), 256>>>(x);
    k4_intranorm<<<N_ * K_, 128>>>(cent, out);
    k5_globalnorm<<<(N_ * K_ * C_) / 256, 256>>>(out);
}

// round 2
// speedup vs baseline: 1.0808x; 1.0808x over previous
#include <cuda_runtime.h>
#include <math.h>

#define N_ 64
#define C_ 512
#define S_ 1024
#define K_ 64

// Scratch (device globals: allocation-free per harness rules)
__device__ float g_invnorm[N_ * S_];
__device__ float g_a[N_ * K_ * S_];
__device__ float g_asum[N_ * K_];
__device__ float g_vlad[N_ * K_ * C_];
__device__ float g_nsum[N_];

// ---- packed fp32x2 helpers (Blackwell FFMA2) -------------------------------
__device__ __forceinline__ unsigned long long pack2(float v) {
    unsigned long long r;
    asm("mov.b64 %0, {%1, %1};" : "=l"(r) : "r"(__float_as_uint(v)));
    return r;
}
__device__ __forceinline__ void fma2(unsigned long long& d,
                                     unsigned long long a,
                                     unsigned long long b) {
    asm("fma.rn.f32x2 %0, %1, %2, %0;" : "+l"(d) : "l"(a), "l"(b));
}
__device__ __forceinline__ float2 unpack2(unsigned long long v) {
    unsigned int lo, hi;
    asm("mov.b64 {%0, %1}, %2;" : "=r"(lo), "=r"(hi) : "l"(v));
    return make_float2(__uint_as_float(lo), __uint_as_float(hi));
}

// ---------------------------------------------------------------------------
// K1: per-pixel inverse L2 norm over channels; also zero accumulators.
// ---------------------------------------------------------------------------
__global__ void k1_invnorm(const float* __restrict__ x) {
    int idx = blockIdx.x * 256 + threadIdx.x;
    int n = idx >> 10;
    int s = idx & (S_ - 1);
    const float* p = x + (size_t)n * C_ * S_ + s;
    float acc = 0.f;
#pragma unroll 8
    for (int c = 0; c < C_; ++c) {
        float v = p[(size_t)c * S_];
        acc += v * v;
    }
    g_invnorm[idx] = 1.f / fmaxf(sqrtf(acc), 1e-12f);

    if (idx < N_ * K_) g_asum[idx] = 0.f;
    if (idx < N_)      g_nsum[idx] = 0.f;
}

// ---------------------------------------------------------------------------
// K2: logits tile (64 x 128) = W(64x512) @ Xn(512 x 128), FFMA2 on k-pairs,
// then softmax over K. grid (8 s-tiles, 64 n), 256 threads.
// Thread tile: 8k (4 k-pairs) x 4s.
// ---------------------------------------------------------------------------
__global__ void k2_gemm1_softmax(const float* __restrict__ x,
                                 const float* __restrict__ w) {
    __shared__ __align__(16) float sh[8256];
    float (*Ws)[66]  = (float (*)[66])sh;            // 32 x 66 = 2112 (8B rows)
    float (*Xs)[132] = (float (*)[132])(sh + 2112);  // 32 x 132 = 4224
    float (*Ls)[129] = (float (*)[129])sh;           // 64 x 129 = 8256 (reuse)

    int n  = blockIdx.y;
    int s0 = blockIdx.x * 128;
    int t  = threadIdx.x;
    int tk = t >> 5, ts = t & 31;
    int k0 = tk * 8, sc0 = ts * 4;

    const float* xn  = x + (size_t)n * C_ * S_;
    const float* inv = g_invnorm + n * S_ + s0;

    unsigned long long acc2[4][4];  // [k-pair][s]
#pragma unroll
    for (int i = 0; i < 4; ++i)
#pragma unroll
        for (int j = 0; j < 4; ++j) acc2[i][j] = 0ull;

    for (int c0 = 0; c0 < C_; c0 += 32) {
        __syncthreads();
        {
            int cc = t & 31, kk = t >> 5;
#pragma unroll
            for (int j = 0; j < 8; ++j) {
                int k = kk + j * 8;
                Ws[cc][k] = w[k * C_ + c0 + cc];
            }
        }
#pragma unroll
        for (int j = 0; j < 16; ++j) {
            int idx = j * 256 + t;
            int cc = idx >> 7, ss = idx & 127;
            Xs[cc][ss] = xn[(size_t)(c0 + cc) * S_ + s0 + ss] * inv[ss];
        }
        __syncthreads();

#pragma unroll 8
        for (int cc = 0; cc < 32; ++cc) {
            unsigned long long wp[4];
#pragma unroll
            for (int i = 0; i < 4; ++i)
                wp[i] = *(const unsigned long long*)&Ws[cc][k0 + 2 * i];
            float4 xv = *(const float4*)&Xs[cc][sc0];
            unsigned long long xx0 = pack2(xv.x), xx1 = pack2(xv.y),
                               xx2 = pack2(xv.z), xx3 = pack2(xv.w);
#pragma unroll
            for (int i = 0; i < 4; ++i) {
                fma2(acc2[i][0], wp[i], xx0);
                fma2(acc2[i][1], wp[i], xx1);
                fma2(acc2[i][2], wp[i], xx2);
                fma2(acc2[i][3], wp[i], xx3);
            }
        }
    }

    __syncthreads();
#pragma unroll
    for (int i = 0; i < 4; ++i)
#pragma unroll
        for (int j = 0; j < 4; ++j) {
            float2 v = unpack2(acc2[i][j]);
            Ls[k0 + 2 * i][sc0 + j]     = v.x;
            Ls[k0 + 2 * i + 1][sc0 + j] = v.y;
        }
    __syncthreads();

    if (t < 128) {
        int s = t;
        float m = -1e30f;
#pragma unroll
        for (int k = 0; k < K_; ++k) m = fmaxf(m, Ls[k][s]);
        float sum = 0.f;
#pragma unroll
        for (int k = 0; k < K_; ++k) {
            float e = expf(Ls[k][s] - m);
            Ls[k][s] = e;
            sum += e;
        }
        float r = 1.f / sum;
#pragma unroll
        for (int k = 0; k < K_; ++k) {
            float a = Ls[k][s] * r;
            Ls[k][s] = a;
            g_a[((size_t)n * K_ + k) * S_ + s0 + s] = a;
        }
    }
    __syncthreads();
    if (t < K_) {
        float ssum = 0.f;
#pragma unroll
        for (int ss = 0; ss < 128; ++ss) ssum += Ls[t][ss];
        atomicAdd(&g_asum[n * K_ + t], ssum);
    }
}

// ---------------------------------------------------------------------------
// K3: vlad tile (64 x 128) = A(64x1024) @ Xn^T, FFMA2 on k-pairs.
// grid (4 c-tiles, 64 n), 256 threads, S tiled by 32.
// ---------------------------------------------------------------------------
__global__ void k3_gemm2(const float* __restrict__ x) {
    __shared__ __align__(16) float As[32][66];
    __shared__ __align__(16) float Xs[32][132];

    int n  = blockIdx.y;
    int c0 = blockIdx.x * 128;
    int t  = threadIdx.x;
    int tk = t >> 5, tc = t & 31;
    int k0 = tk * 8, cc0 = tc * 4;

    const float* xn  = x + (size_t)n * C_ * S_;
    const float* an  = g_a + (size_t)n * K_ * S_;
    const float* inv = g_invnorm + n * S_;

    unsigned long long acc2[4][4];  // [k-pair][c]
#pragma unroll
    for (int i = 0; i < 4; ++i)
#pragma unroll
        for (int j = 0; j < 4; ++j) acc2[i][j] = 0ull;

    for (int s0 = 0; s0 < S_; s0 += 32) {
        __syncthreads();
        {
            int ss = t & 31, kk = t >> 5;
#pragma unroll
            for (int j = 0; j < 8; ++j) {
                int k = kk + j * 8;
                As[ss][k] = an[(size_t)k * S_ + s0 + ss];
            }
        }
#pragma unroll
        for (int j = 0; j < 16; ++j) {
            int idx = j * 256 + t;
            int ci = idx >> 5, ss = idx & 31;
            Xs[ss][ci] = xn[(size_t)(c0 + ci) * S_ + s0 + ss] * inv[s0 + ss];
        }
        __syncthreads();

#pragma unroll 8
        for (int ss = 0; ss < 32; ++ss) {
            unsigned long long ap[4];
#pragma unroll
            for (int i = 0; i < 4; ++i)
                ap[i] = *(const unsigned long long*)&As[ss][k0 + 2 * i];
            float4 xv = *(const float4*)&Xs[ss][cc0];
            unsigned long long xx0 = pack2(xv.x), xx1 = pack2(xv.y),
                               xx2 = pack2(xv.z), xx3 = pack2(xv.w);
#pragma unroll
            for (int i = 0; i < 4; ++i) {
                fma2(acc2[i][0], ap[i], xx0);
                fma2(acc2[i][1], ap[i], xx1);
                fma2(acc2[i][2], ap[i], xx2);
                fma2(acc2[i][3], ap[i], xx3);
            }
        }
    }

#pragma unroll
    for (int i = 0; i < 4; ++i) {
        float2 v0 = unpack2(acc2[i][0]);
        float2 v1 = unpack2(acc2[i][1]);
        float2 v2 = unpack2(acc2[i][2]);
        float2 v3 = unpack2(acc2[i][3]);
        float4 lo = make_float4(v0.x, v1.x, v2.x, v3.x);
        float4 hi = make_float4(v0.y, v1.y, v2.y, v3.y);
        *(float4*)&g_vlad[((size_t)n * K_ + (k0 + 2 * i)) * C_ + c0 + cc0]     = lo;
        *(float4*)&g_vlad[((size_t)n * K_ + (k0 + 2 * i + 1)) * C_ + c0 + cc0] = hi;
    }
}

// ---------------------------------------------------------------------------
// K4: per-(n,k): subtract asum*centroid, intra-normalize, write out, per-n sumsq.
// ---------------------------------------------------------------------------
__global__ void k4_intranorm(const float* __restrict__ centroids,
                             float* __restrict__ out) {
    int nk = blockIdx.x;
    int n = nk >> 6, k = nk & 63;
    int t = threadIdx.x;

    float asum = g_asum[nk];
    float v[4];
    float ss = 0.f;
#pragma unroll
    for (int j = 0; j < 4; ++j) {
        int c = t + j * 128;
        float val = g_vlad[(size_t)nk * C_ + c] - asum * centroids[k * C_ + c];
        v[j] = val;
        ss += val * val;
    }
#pragma unroll
    for (int o = 16; o; o >>= 1) ss += __shfl_xor_sync(0xffffffffu, ss, o);
    __shared__ float red[4];
    if ((t & 31) == 0) red[t >> 5] = ss;
    __syncthreads();
    float total = red[0] + red[1] + red[2] + red[3];

    float invn = 1.f / fmaxf(sqrtf(total), 1e-12f);
    if (t == 0) atomicAdd(&g_nsum[n], total * invn * invn);

#pragma unroll
    for (int j = 0; j < 4; ++j) {
        int c = t + j * 128;
        out[(size_t)n * (K_ * C_) + k * C_ + c] = v[j] * invn;
    }
}

// ---------------------------------------------------------------------------
// K5: global L2 normalization per n.
// ---------------------------------------------------------------------------
__global__ void k5_globalnorm(float* __restrict__ out) {
    int idx = blockIdx.x * 256 + threadIdx.x;
    int n = idx >> 15;
    float g = g_nsum[n];
    out[idx] *= 1.f / fmaxf(sqrtf(g), 1e-12f);
}

// ---------------------------------------------------------------------------
extern "C" void kernel_launch(void* const* d_in, const int* in_sizes, int n_in,
                              void* d_out, int out_size) {
    const float* x    = (const float*)d_in[0];
    const float* w    = (const float*)d_in[1];
    const float* cent = (const float*)d_in[2];
    float* out = (float*)d_out;

    k1_invnorm<<<(N_ * S_) / 256, 256>>>(x);
    k2_gemm1_softmax<<<dim3(S_ / 128, N_), 256>>>(x, w);
    k3_gemm2<<<dim3(C_ / 128, N_), 256>>>(x);
    k4_intranorm<<<N_ * K_, 128>>>(cent, out);
    k5_globalnorm<<<(N_ * K_ * C_) / 256, 256>>>(out);
}

// round 4
// speedup vs baseline: 2.0341x; 1.8821x over previous
#include <cuda_runtime.h>
#include <cuda_bf16.h>
#include <math.h>
#include <stdint.h>

#define N_ 64
#define C_ 512
#define S_ 1024
#define K_ 64

// ---- scratch (device globals; allocation-free) ------------------------------
__device__ uint32_t g_wpk[K_ * C_];        // w packed bf16 (hi | lo<<16)
__device__ uint32_t g_apk[N_ * K_ * S_];   // a' = softmax*invnorm, packed bf16
__device__ float    g_asum[N_ * K_];
__device__ float    g_vlad[N_ * K_ * C_];
__device__ float    g_nsum[N_];

// ---- helpers ----------------------------------------------------------------
__device__ __forceinline__ uint32_t smem_u32(const void* p) {
    return (uint32_t)__cvta_generic_to_shared((void*)p);
}
__device__ __forceinline__ void sts32(uint32_t addr, uint32_t v) {
    asm volatile("st.shared.b32 [%0], %1;" :: "r"(addr), "r"(v));
}
__device__ __forceinline__ void ldmx4(uint32_t r[4], uint32_t addr) {
    asm volatile("ldmatrix.sync.aligned.m8n8.x4.shared.b16 {%0,%1,%2,%3}, [%4];"
                 : "=r"(r[0]), "=r"(r[1]), "=r"(r[2]), "=r"(r[3]) : "r"(addr));
}
__device__ __forceinline__ void mma16816(float d[4], const uint32_t a[4],
                                         const uint32_t b[2]) {
    asm volatile(
        "mma.sync.aligned.m16n8k16.row.col.f32.bf16.bf16.f32 "
        "{%0,%1,%2,%3}, {%4,%5,%6,%7}, {%8,%9}, {%0,%1,%2,%3};"
        : "+f"(d[0]), "+f"(d[1]), "+f"(d[2]), "+f"(d[3])
        : "r"(a[0]), "r"(a[1]), "r"(a[2]), "r"(a[3]), "r"(b[0]), "r"(b[1]));
}
// bf16 hi/lo split
__device__ __forceinline__ void split2(float f0, float f1, uint32_t& hw, uint32_t& lw) {
    __nv_bfloat16 h0 = __float2bfloat16(f0), h1 = __float2bfloat16(f1);
    float r0 = f0 - __bfloat162float(h0);
    float r1 = f1 - __bfloat162float(h1);
    __nv_bfloat16 l0 = __float2bfloat16(r0), l1 = __float2bfloat16(r1);
    hw = (uint32_t)__bfloat16_as_ushort(h0) | ((uint32_t)__bfloat16_as_ushort(h1) << 16);
    lw = (uint32_t)__bfloat16_as_ushort(l0) | ((uint32_t)__bfloat16_as_ushort(l1) << 16);
}
__device__ __forceinline__ uint32_t split1(float f) {
    __nv_bfloat16 h = __float2bfloat16(f);
    __nv_bfloat16 l = __float2bfloat16(f - __bfloat162float(h));
    return (uint32_t)__bfloat16_as_ushort(h) | ((uint32_t)__bfloat16_as_ushort(l) << 16);
}

// smem tile layout: rows padded to 144B (72 bf16) -> conflict-free ldmatrix
#define RS 144
#define OFF_AH 0
#define OFF_AL 18432
#define OFF_BH 36864
#define OFF_BL 46080
#define SMEM_DYN 55296
#define LS_STRIDE 66

extern __shared__ char dsm[];

// ---------------------------------------------------------------------------
// k0: pack w to bf16 hi/lo; zero accumulators.
// ---------------------------------------------------------------------------
__global__ void k0_prep(const float* __restrict__ w) {
    int i = blockIdx.x * 256 + threadIdx.x;  // 32768
    g_wpk[i] = split1(w[i]);
    if (i < N_ * K_) g_asum[i] = 0.f;
    if (i < N_)      g_nsum[i] = 0.f;
}

// ---------------------------------------------------------------------------
// shared mma core: D[128 rows][64 cols] += A[128][64] * B[64][64]^T (k-major
// contraction over 64), 3-term bf16 hi/lo. Called once per chunk.
// acc[mt][nt][4]: warp w owns rows w*32 + mt*16 + frag rows.
// ---------------------------------------------------------------------------
__device__ __forceinline__ void mma_chunk(uint32_t Ah, uint32_t Al,
                                          uint32_t Bh, uint32_t Bl,
                                          float acc[2][8][4], int w, int lane) {
    int arow = lane & 15;
    int asel = (lane >> 4) * 16;
    int brow = (lane & 7) + ((lane >> 4) << 3);
    int bsel = ((lane >> 3) & 1) * 16;

#pragma unroll
    for (int term = 0; term < 3; ++term) {
        uint32_t Ab = (term == 2) ? Al : Ah;
        uint32_t Bb = (term == 1) ? Bl : Bh;
#pragma unroll
        for (int ks = 0; ks < 4; ++ks) {
            int kb = ks * 32;
            uint32_t a[2][4];
#pragma unroll
            for (int mt = 0; mt < 2; ++mt)
                ldmx4(a[mt], Ab + (w * 32 + mt * 16 + arow) * RS + kb + asel);
            uint32_t b[8][2];
#pragma unroll
            for (int p = 0; p < 4; ++p) {
                uint32_t r[4];
                ldmx4(r, Bb + (p * 16 + brow) * RS + kb + bsel);
                b[2 * p][0] = r[0]; b[2 * p][1] = r[1];
                b[2 * p + 1][0] = r[2]; b[2 * p + 1][1] = r[3];
            }
#pragma unroll
            for (int mt = 0; mt < 2; ++mt)
#pragma unroll
                for (int nt = 0; nt < 8; ++nt)
                    mma16816(acc[mt][nt], a[mt], b[nt]);
        }
    }
}

__device__ __forceinline__ void store_frags(float* Ls, float acc[2][8][4],
                                            int w, int lane) {
#pragma unroll
    for (int mt = 0; mt < 2; ++mt)
#pragma unroll
        for (int nt = 0; nt < 8; ++nt) {
            int r0 = w * 32 + mt * 16 + (lane >> 2);
            int c = nt * 8 + (lane & 3) * 2;
            Ls[r0 * LS_STRIDE + c]           = acc[mt][nt][0];
            Ls[r0 * LS_STRIDE + c + 1]       = acc[mt][nt][1];
            Ls[(r0 + 8) * LS_STRIDE + c]     = acc[mt][nt][2];
            Ls[(r0 + 8) * LS_STRIDE + c + 1] = acc[mt][nt][3];
        }
}

// ---------------------------------------------------------------------------
// g1: logits D[s=128,k=64] = X^T·W^T over C (8 chunks of 64), then invnorm
// scale + softmax over k; emit a' (packed bf16 hi/lo) and asum.
// ---------------------------------------------------------------------------
__global__ void __launch_bounds__(128) g1_logits(const float* __restrict__ x) {
    uint32_t sb = smem_u32(dsm);
    uint32_t Ah = sb + OFF_AH, Al = sb + OFF_AL, Bh = sb + OFF_BH, Bl = sb + OFF_BL;
    int t = threadIdx.x, w = t >> 5, lane = t & 31;
    int n = blockIdx.y, s0 = blockIdx.x * 128;
    const float* xn = x + (size_t)n * C_ * S_ + s0;

    float acc[2][8][4];
#pragma unroll
    for (int i = 0; i < 2; ++i)
#pragma unroll
        for (int j = 0; j < 8; ++j)
#pragma unroll
            for (int q = 0; q < 4; ++q) acc[i][j][q] = 0.f;
    float sumsq = 0.f;

    for (int ch = 0; ch < 8; ++ch) {
        __syncthreads();
        int cc0 = ch * 64;
        // A = x^T tile [128 s][64 c]: thread t <-> column s0+t (transpose store)
#pragma unroll
        for (int cp = 0; cp < 32; ++cp) {
            float f0 = xn[(size_t)(cc0 + 2 * cp) * S_ + t];
            float f1 = xn[(size_t)(cc0 + 2 * cp + 1) * S_ + t];
            sumsq += f0 * f0 + f1 * f1;
            uint32_t hw, lw;
            split2(f0, f1, hw, lw);
            sts32(Ah + t * RS + cp * 4, hw);
            sts32(Al + t * RS + cp * 4, lw);
        }
        // B = w tile [64 k][64 c] from packed global
#pragma unroll
        for (int j = 0; j < 16; ++j) {
            int k = j * 4 + w;
            uint2 v = *(const uint2*)&g_wpk[k * C_ + cc0 + lane * 2];
            sts32(Bh + k * RS + lane * 4, __byte_perm(v.x, v.y, 0x5410));
            sts32(Bl + k * RS + lane * 4, __byte_perm(v.x, v.y, 0x7632));
        }
        __syncthreads();
        mma_chunk(Ah, Al, Bh, Bl, acc, w, lane);
    }

    __syncthreads();
    float* Ls = (float*)dsm;
    store_frags(Ls, acc, w, lane);
    __syncthreads();

    // softmax over k for row s=t; logits scaled by invnorm(s)
    float inv = 1.f / fmaxf(sqrtf(sumsq), 1e-12f);
    float m = -1e30f;
#pragma unroll
    for (int k = 0; k < K_; ++k) m = fmaxf(m, Ls[t * LS_STRIDE + k] * inv);
    float sum = 0.f;
#pragma unroll
    for (int k = 0; k < K_; ++k) {
        float e = expf(Ls[t * LS_STRIDE + k] * inv - m);
        Ls[t * LS_STRIDE + k] = e;
        sum += e;
    }
    float rs = 1.f / sum;
#pragma unroll
    for (int k = 0; k < K_; ++k) {
        float a = Ls[t * LS_STRIDE + k] * rs;
        Ls[t * LS_STRIDE + k] = a;                                   // unscaled
        g_apk[(((size_t)n * K_ + k) << 10) + s0 + t] = split1(a * inv); // scaled
    }
    __syncthreads();
    if (t < K_) {
        float s = 0.f;
#pragma unroll
        for (int si = 0; si < 128; ++si) s += Ls[si * LS_STRIDE + t];
        atomicAdd(&g_asum[n * K_ + t], s);
    }
}

// ---------------------------------------------------------------------------
// g2: vlad D[c=128,k=64] = X·A'^T over S (16 chunks of 64). Natural layouts.
// ---------------------------------------------------------------------------
__global__ void __launch_bounds__(128) g2_vlad(const float* __restrict__ x) {
    uint32_t sb = smem_u32(dsm);
    uint32_t Ah = sb + OFF_AH, Al = sb + OFF_AL, Bh = sb + OFF_BH, Bl = sb + OFF_BL;
    int t = threadIdx.x, w = t >> 5, lane = t & 31;
    int n = blockIdx.y, c0 = blockIdx.x * 128;
    const float* xn = x + (size_t)n * C_ * S_;

    float acc[2][8][4];
#pragma unroll
    for (int i = 0; i < 2; ++i)
#pragma unroll
        for (int j = 0; j < 8; ++j)
#pragma unroll
            for (int q = 0; q < 4; ++q) acc[i][j][q] = 0.f;

    for (int ch = 0; ch < 16; ++ch) {
        __syncthreads();
        int ss0 = ch * 64;
        // A = x tile [128 c][64 s]
#pragma unroll
        for (int j = 0; j < 32; ++j) {
            int c = j * 4 + w;
            float2 v = *(const float2*)&xn[(size_t)(c0 + c) * S_ + ss0 + lane * 2];
            uint32_t hw, lw;
            split2(v.x, v.y, hw, lw);
            sts32(Ah + c * RS + lane * 4, hw);
            sts32(Al + c * RS + lane * 4, lw);
        }
        // B = a' tile [64 k][64 s]
#pragma unroll
        for (int j = 0; j < 16; ++j) {
            int k = j * 4 + w;
            uint2 v = *(const uint2*)&g_apk[(((size_t)n * K_ + k) << 10) + ss0 + lane * 2];
            sts32(Bh + k * RS + lane * 4, __byte_perm(v.x, v.y, 0x5410));
            sts32(Bl + k * RS + lane * 4, __byte_perm(v.x, v.y, 0x7632));
        }
        __syncthreads();
        mma_chunk(Ah, Al, Bh, Bl, acc, w, lane);
    }

    __syncthreads();
    float* Ds = (float*)dsm;
    store_frags(Ds, acc, w, lane);
    __syncthreads();

    // write D^T: vlad[n][k][c0+t] = Ds[t][k], coalesced over t
#pragma unroll 4
    for (int k = 0; k < K_; ++k)
        g_vlad[(((size_t)n * K_ + k) << 9) + c0 + t] = Ds[t * LS_STRIDE + k];
}

// ---------------------------------------------------------------------------
// k4: per-(n,k): subtract asum*centroid, intra-normalize, write out, per-n sumsq.
// ---------------------------------------------------------------------------
__global__ void k4_intranorm(const float* __restrict__ centroids,
                             float* __restrict__ out) {
    int nk = blockIdx.x;
    int n = nk >> 6, k = nk & 63;
    int t = threadIdx.x;

    float asum = g_asum[nk];
    float v[4];
    float ss = 0.f;
#pragma unroll
    for (int j = 0; j < 4; ++j) {
        int c = t + j * 128;
        float val = g_vlad[(size_t)nk * C_ + c] - asum * centroids[k * C_ + c];
        v[j] = val;
        ss += val * val;
    }
#pragma unroll
    for (int o = 16; o; o >>= 1) ss += __shfl_xor_sync(0xffffffffu, ss, o);
    __shared__ float red[4];
    if ((t & 31) == 0) red[t >> 5] = ss;
    __syncthreads();
    float total = red[0] + red[1] + red[2] + red[3];

    float invn = 1.f / fmaxf(sqrtf(total), 1e-12f);
    if (t == 0) atomicAdd(&g_nsum[n], total * invn * invn);

#pragma unroll
    for (int j = 0; j < 4; ++j) {
        int c = t + j * 128;
        out[(size_t)n * (K_ * C_) + k * C_ + c] = v[j] * invn;
    }
}

// ---------------------------------------------------------------------------
// k5: global L2 normalization per n.
// ---------------------------------------------------------------------------
__global__ void k5_globalnorm(float* __restrict__ out) {
    int idx = blockIdx.x * 256 + threadIdx.x;
    int n = idx >> 15;
    float g = g_nsum[n];
    out[idx] *= 1.f / fmaxf(sqrtf(g), 1e-12f);
}

// ---------------------------------------------------------------------------
extern "C" void kernel_launch(void* const* d_in, const int* in_sizes, int n_in,
                              void* d_out, int out_size) {
    const float* x    = (const float*)d_in[0];
    const float* w    = (const float*)d_in[1];
    const float* cent = (const float*)d_in[2];
    float* out = (float*)d_out;

    static int smem_set = 0;
    if (!smem_set) {
        cudaFuncSetAttribute(g1_logits, cudaFuncAttributeMaxDynamicSharedMemorySize, SMEM_DYN);
        cudaFuncSetAttribute(g2_vlad,   cudaFuncAttributeMaxDynamicSharedMemorySize, SMEM_DYN);
        smem_set = 1;
    }

    k0_prep<<<(K_ * C_) / 256, 256>>>(w);
    g1_logits<<<dim3(S_ / 128, N_), 128, SMEM_DYN>>>(x);
    g2_vlad<<<dim3(C_ / 128, N_), 128, SMEM_DYN>>>(x);
    k4_intranorm<<<N_ * K_, 128>>>(cent, out);
    k5_globalnorm<<<(N_ * K_ * C_) / 256, 256>>>(out);
}

// round 5
// speedup vs baseline: 2.2304x; 1.0965x over previous
#include <cuda_runtime.h>
#include <cuda_bf16.h>
#include <math.h>
#include <stdint.h>

#define N_ 64
#define C_ 512
#define S_ 1024
#define K_ 64

// ---- scratch (device globals; allocation-free) ------------------------------
__device__ __nv_bfloat16 g_wh[K_ * C_], g_wl[K_ * C_];       // w split
__device__ __nv_bfloat16 g_ah[N_ * K_ * S_], g_al[N_ * K_ * S_]; // a' split
__device__ float g_asum[N_ * K_];
__device__ float g_vlad[N_ * K_ * C_];
__device__ float g_nsum[N_];

// ---- helpers ----------------------------------------------------------------
__device__ __forceinline__ uint32_t smem_u32(const void* p) {
    return (uint32_t)__cvta_generic_to_shared((void*)p);
}
__device__ __forceinline__ void sts32(uint32_t addr, uint32_t v) {
    asm volatile("st.shared.b32 [%0], %1;" :: "r"(addr), "r"(v));
}
__device__ __forceinline__ void cpa16(uint32_t dst, const void* src) {
    asm volatile("cp.async.cg.shared.global [%0], [%1], 16;" :: "r"(dst), "l"(src));
}
#define CP_COMMIT() asm volatile("cp.async.commit_group;" ::: "memory")
template <int N>
__device__ __forceinline__ void cp_wait() {
    asm volatile("cp.async.wait_group %0;" :: "n"(N) : "memory");
}
__device__ __forceinline__ void ldmx4(uint32_t r[4], uint32_t addr) {
    asm volatile("ldmatrix.sync.aligned.m8n8.x4.shared.b16 {%0,%1,%2,%3}, [%4];"
                 : "=r"(r[0]), "=r"(r[1]), "=r"(r[2]), "=r"(r[3]) : "r"(addr));
}
__device__ __forceinline__ void mma16816(float d[4], const uint32_t a[4],
                                         const uint32_t b[2]) {
    asm volatile(
        "mma.sync.aligned.m16n8k16.row.col.f32.bf16.bf16.f32 "
        "{%0,%1,%2,%3}, {%4,%5,%6,%7}, {%8,%9}, {%0,%1,%2,%3};"
        : "+f"(d[0]), "+f"(d[1]), "+f"(d[2]), "+f"(d[3])
        : "r"(a[0]), "r"(a[1]), "r"(a[2]), "r"(a[3]), "r"(b[0]), "r"(b[1]));
}
__device__ __forceinline__ void split2(float f0, float f1, uint32_t& hw, uint32_t& lw) {
    __nv_bfloat16 h0 = __float2bfloat16(f0), h1 = __float2bfloat16(f1);
    float r0 = f0 - __bfloat162float(h0);
    float r1 = f1 - __bfloat162float(h1);
    __nv_bfloat16 l0 = __float2bfloat16(r0), l1 = __float2bfloat16(r1);
    hw = (uint32_t)__bfloat16_as_ushort(h0) | ((uint32_t)__bfloat16_as_ushort(h1) << 16);
    lw = (uint32_t)__bfloat16_as_ushort(l0) | ((uint32_t)__bfloat16_as_ushort(l1) << 16);
}

// smem layout (both gemm kernels): A single-buffered, B double-buffered.
#define RS 144
#define OAH 0
#define OAL 18432
#define OBH 36864
#define OBL 55296
#define BBUF 9216
#define SMEM_DYN 73728
#define LS_STRIDE 66

extern __shared__ char dsm[];

// ---------------------------------------------------------------------------
// k0: split w into g_wh/g_wl; zero accumulators.
// ---------------------------------------------------------------------------
__global__ void k0_prep(const float* __restrict__ w) {
    int i = blockIdx.x * 256 + threadIdx.x;  // 32768
    float f = w[i];
    __nv_bfloat16 h = __float2bfloat16(f);
    g_wh[i] = h;
    g_wl[i] = __float2bfloat16(f - __bfloat162float(h));
    if (i < N_ * K_) g_asum[i] = 0.f;
    if (i < N_)      g_nsum[i] = 0.f;
}

// ---------------------------------------------------------------------------
// B tile stage via cp.async: 64 rows x 64 bf16 (128B/row) from [r*ld + coff].
// ---------------------------------------------------------------------------
__device__ __forceinline__ void stageB(uint32_t BhD, uint32_t BlD,
                                       const __nv_bfloat16* __restrict__ srcH,
                                       const __nv_bfloat16* __restrict__ srcL,
                                       int ld, int coff, int t) {
    int r0 = t >> 3;
    int cc = (t & 7) * 8;
#pragma unroll
    for (int it = 0; it < 4; ++it) {
        int r = it * 16 + r0;
        cpa16(BhD + r * RS + cc * 2, srcH + (size_t)r * ld + coff + cc);
        cpa16(BlD + r * RS + cc * 2, srcL + (size_t)r * ld + coff + cc);
    }
}

// ---------------------------------------------------------------------------
// mma core (identical to round 4): D[128][64] += A[128][64]*B[64][64]^T, 3-term.
// ---------------------------------------------------------------------------
__device__ __forceinline__ void mma_chunk(uint32_t Ah, uint32_t Al,
                                          uint32_t Bh, uint32_t Bl,
                                          float acc[2][8][4], int w, int lane) {
    int arow = lane & 15;
    int asel = (lane >> 4) * 16;
    int brow = (lane & 7) + ((lane >> 4) << 3);
    int bsel = ((lane >> 3) & 1) * 16;

#pragma unroll
    for (int term = 0; term < 3; ++term) {
        uint32_t Ab = (term == 2) ? Al : Ah;
        uint32_t Bb = (term == 1) ? Bl : Bh;
#pragma unroll
        for (int ks = 0; ks < 4; ++ks) {
            int kb = ks * 32;
            uint32_t a[2][4];
#pragma unroll
            for (int mt = 0; mt < 2; ++mt)
                ldmx4(a[mt], Ab + (w * 32 + mt * 16 + arow) * RS + kb + asel);
            uint32_t b[8][2];
#pragma unroll
            for (int p = 0; p < 4; ++p) {
                uint32_t r[4];
                ldmx4(r, Bb + (p * 16 + brow) * RS + kb + bsel);
                b[2 * p][0] = r[0]; b[2 * p][1] = r[1];
                b[2 * p + 1][0] = r[2]; b[2 * p + 1][1] = r[3];
            }
#pragma unroll
            for (int mt = 0; mt < 2; ++mt)
#pragma unroll
                for (int nt = 0; nt < 8; ++nt)
                    mma16816(acc[mt][nt], a[mt], b[nt]);
        }
    }
}

__device__ __forceinline__ void store_frags(float* Ls, float acc[2][8][4],
                                            int w, int lane) {
#pragma unroll
    for (int mt = 0; mt < 2; ++mt)
#pragma unroll
        for (int nt = 0; nt < 8; ++nt) {
            int r0 = w * 32 + mt * 16 + (lane >> 2);
            int c = nt * 8 + (lane & 3) * 2;
            Ls[r0 * LS_STRIDE + c]           = acc[mt][nt][0];
            Ls[r0 * LS_STRIDE + c + 1]       = acc[mt][nt][1];
            Ls[(r0 + 8) * LS_STRIDE + c]     = acc[mt][nt][2];
            Ls[(r0 + 8) * LS_STRIDE + c + 1] = acc[mt][nt][3];
        }
}

// ---------------------------------------------------------------------------
// g1: logits D[s=128,k=64] over C (8 chunks). x prefetched to regs; B cp.async.
// Epilogue: invnorm scale + softmax over k; write a' split bf16 + asum.
// ---------------------------------------------------------------------------
__global__ void __launch_bounds__(128) g1_logits(const float* __restrict__ x) {
    uint32_t sb = smem_u32(dsm);
    uint32_t Ah = sb + OAH, Al = sb + OAL;
    int t = threadIdx.x, w = t >> 5, lane = t & 31;
    int n = blockIdx.y, s0 = blockIdx.x * 128;
    const float* xn = x + (size_t)n * C_ * S_ + s0;

    float acc[2][8][4];
#pragma unroll
    for (int i = 0; i < 2; ++i)
#pragma unroll
        for (int j = 0; j < 8; ++j)
#pragma unroll
            for (int q = 0; q < 4; ++q) acc[i][j][q] = 0.f;
    float sumsq = 0.f;

    float xr[64];
#pragma unroll
    for (int cp = 0; cp < 64; ++cp) xr[cp] = xn[(size_t)cp * S_ + t];
    stageB(sb + OBH, sb + OBL, g_wh, g_wl, C_, 0, t);
    CP_COMMIT();

    for (int ch = 0; ch < 8; ++ch) {
        __syncthreads();   // A tile free (prev mma done)
        // convert prefetched regs -> A tiles; accumulate sumsq for s = s0+t
#pragma unroll
        for (int cp = 0; cp < 32; ++cp) {
            float f0 = xr[2 * cp], f1 = xr[2 * cp + 1];
            sumsq += f0 * f0 + f1 * f1;
            uint32_t hw, lw;
            split2(f0, f1, hw, lw);
            sts32(Ah + t * RS + cp * 4, hw);
            sts32(Al + t * RS + cp * 4, lw);
        }
        if (ch < 7) {
            int cc0 = (ch + 1) * 64;
#pragma unroll
            for (int cp = 0; cp < 64; ++cp) xr[cp] = xn[(size_t)(cc0 + cp) * S_ + t];
            stageB(sb + OBH + ((ch + 1) & 1) * BBUF, sb + OBL + ((ch + 1) & 1) * BBUF,
                   g_wh, g_wl, C_, cc0, t);
            CP_COMMIT();
            cp_wait<1>();
        } else {
            cp_wait<0>();
        }
        __syncthreads();
        mma_chunk(Ah, Al, sb + OBH + (ch & 1) * BBUF, sb + OBL + (ch & 1) * BBUF,
                  acc, w, lane);
    }

    __syncthreads();
    float* Ls = (float*)dsm;
    store_frags(Ls, acc, w, lane);
    __syncthreads();

    // softmax over k for s = s0+t; logits scaled by invnorm(s)
    float inv = 1.f / fmaxf(sqrtf(sumsq), 1e-12f);
    float m = -1e30f;
#pragma unroll
    for (int k = 0; k < K_; ++k) m = fmaxf(m, Ls[t * LS_STRIDE + k] * inv);
    float sum = 0.f;
#pragma unroll
    for (int k = 0; k < K_; ++k) {
        float e = expf(Ls[t * LS_STRIDE + k] * inv - m);
        Ls[t * LS_STRIDE + k] = e;
        sum += e;
    }
    float rs = 1.f / sum;
#pragma unroll
    for (int k = 0; k < K_; ++k) {
        float a = Ls[t * LS_STRIDE + k] * rs;
        Ls[t * LS_STRIDE + k] = a;                  // unscaled (for asum)
        float ap = a * inv;                          // a' = a * invnorm
        __nv_bfloat16 h = __float2bfloat16(ap);
        size_t idx = (((size_t)n * K_ + k) << 10) + s0 + t;
        g_ah[idx] = h;
        g_al[idx] = __float2bfloat16(ap - __bfloat162float(h));
    }
    __syncthreads();
    if (t < K_) {
        float s = 0.f;
#pragma unroll
        for (int si = 0; si < 128; ++si) s += Ls[si * LS_STRIDE + t];
        atomicAdd(&g_asum[n * K_ + t], s);
    }
}

// ---------------------------------------------------------------------------
// g2: vlad D[c=128,k=64] over S (16 chunks). x prefetched to regs; B cp.async.
// ---------------------------------------------------------------------------
__global__ void __launch_bounds__(128) g2_vlad(const float* __restrict__ x) {
    uint32_t sb = smem_u32(dsm);
    uint32_t Ah = sb + OAH, Al = sb + OAL;
    int t = threadIdx.x, w = t >> 5, lane = t & 31;
    int n = blockIdx.y, c0 = blockIdx.x * 128;
    const float* xn = x + (size_t)n * C_ * S_;
    const __nv_bfloat16* ahn = g_ah + (size_t)n * K_ * S_;
    const __nv_bfloat16* aln = g_al + (size_t)n * K_ * S_;

    float acc[2][8][4];
#pragma unroll
    for (int i = 0; i < 2; ++i)
#pragma unroll
        for (int j = 0; j < 8; ++j)
#pragma unroll
            for (int q = 0; q < 4; ++q) acc[i][j][q] = 0.f;

    float2 xr[32];
#pragma unroll
    for (int j = 0; j < 32; ++j) {
        int c = j * 4 + w;
        xr[j] = *(const float2*)&xn[(size_t)(c0 + c) * S_ + lane * 2];
    }
    stageB(sb + OBH, sb + OBL, ahn, aln, S_, 0, t);
    CP_COMMIT();

    for (int ch = 0; ch < 16; ++ch) {
        __syncthreads();
#pragma unroll
        for (int j = 0; j < 32; ++j) {
            int c = j * 4 + w;
            uint32_t hw, lw;
            split2(xr[j].x, xr[j].y, hw, lw);
            sts32(Ah + c * RS + lane * 4, hw);
            sts32(Al + c * RS + lane * 4, lw);
        }
        if (ch < 15) {
            int ss0 = (ch + 1) * 64;
#pragma unroll
            for (int j = 0; j < 32; ++j) {
                int c = j * 4 + w;
                xr[j] = *(const float2*)&xn[(size_t)(c0 + c) * S_ + ss0 + lane * 2];
            }
            stageB(sb + OBH + ((ch + 1) & 1) * BBUF, sb + OBL + ((ch + 1) & 1) * BBUF,
                   ahn, aln, S_, ss0, t);
            CP_COMMIT();
            cp_wait<1>();
        } else {
            cp_wait<0>();
        }
        __syncthreads();
        mma_chunk(Ah, Al, sb + OBH + (ch & 1) * BBUF, sb + OBL + (ch & 1) * BBUF,
                  acc, w, lane);
    }

    __syncthreads();
    float* Ds = (float*)dsm;
    store_frags(Ds, acc, w, lane);
    __syncthreads();

#pragma unroll 4
    for (int k = 0; k < K_; ++k)
        g_vlad[(((size_t)n * K_ + k) << 9) + c0 + t] = Ds[t * LS_STRIDE + k];
}

// ---------------------------------------------------------------------------
// k4: per-(n,k): subtract asum*centroid, intra-normalize, write out, per-n sumsq.
// ---------------------------------------------------------------------------
__global__ void k4_intranorm(const float* __restrict__ centroids,
                             float* __restrict__ out) {
    int nk = blockIdx.x;
    int n = nk >> 6, k = nk & 63;
    int t = threadIdx.x;

    float asum = g_asum[nk];
    float v[4];
    float ss = 0.f;
#pragma unroll
    for (int j = 0; j < 4; ++j) {
        int c = t + j * 128;
        float val = g_vlad[(size_t)nk * C_ + c] - asum * centroids[k * C_ + c];
        v[j] = val;
        ss += val * val;
    }
#pragma unroll
    for (int o = 16; o; o >>= 1) ss += __shfl_xor_sync(0xffffffffu, ss, o);
    __shared__ float red[4];
    if ((t & 31) == 0) red[t >> 5] = ss;
    __syncthreads();
    float total = red[0] + red[1] + red[2] + red[3];

    float invn = 1.f / fmaxf(sqrtf(total), 1e-12f);
    if (t == 0) atomicAdd(&g_nsum[n], total * invn * invn);

#pragma unroll
    for (int j = 0; j < 4; ++j) {
        int c = t + j * 128;
        out[(size_t)n * (K_ * C_) + k * C_ + c] = v[j] * invn;
    }
}

// ---------------------------------------------------------------------------
// k5: global L2 normalization per n.
// ---------------------------------------------------------------------------
__global__ void k5_globalnorm(float* __restrict__ out) {
    int idx = blockIdx.x * 256 + threadIdx.x;
    int n = idx >> 15;
    float g = g_nsum[n];
    out[idx] *= 1.f / fmaxf(sqrtf(g), 1e-12f);
}

// ---------------------------------------------------------------------------
extern "C" void kernel_launch(void* const* d_in, const int* in_sizes, int n_in,
                              void* d_out, int out_size) {
    const float* x    = (const float*)d_in[0];
    const float* w    = (const float*)d_in[1];
    const float* cent = (const float*)d_in[2];
    float* out = (float*)d_out;

    static int smem_set = 0;
    if (!smem_set) {
        cudaFuncSetAttribute(g1_logits, cudaFuncAttributeMaxDynamicSharedMemorySize, SMEM_DYN);
        cudaFuncSetAttribute(g2_vlad,   cudaFuncAttributeMaxDynamicSharedMemorySize, SMEM_DYN);
        smem_set = 1;
    }

    k0_prep<<<(K_ * C_) / 256, 256>>>(w);
    g1_logits<<<dim3(S_ / 128, N_), 128, SMEM_DYN>>>(x);
    g2_vlad<<<dim3(C_ / 128, N_), 128, SMEM_DYN>>>(x);
    k4_intranorm<<<N_ * K_, 128>>>(cent, out);
    k5_globalnorm<<<(N_ * K_ * C_) / 256, 256>>>(out);
}

// round 6
// speedup vs baseline: 2.3793x; 1.0668x over previous
#include <cuda_runtime.h>
#include <cuda_bf16.h>
#include <math.h>
#include <stdint.h>

#define N_ 64
#define C_ 512
#define S_ 1024
#define K_ 64

// ---- scratch (device globals; allocation-free) ------------------------------
__device__ __nv_bfloat16 g_wh[K_ * C_], g_wl[K_ * C_];
__device__ __nv_bfloat16 g_ah[N_ * K_ * S_], g_al[N_ * K_ * S_];
__device__ float g_asum[N_ * K_];
__device__ float g_vlad[N_ * K_ * C_];
__device__ float g_nsum[N_];

// ---- helpers ----------------------------------------------------------------
__device__ __forceinline__ uint32_t smem_u32(const void* p) {
    return (uint32_t)__cvta_generic_to_shared((void*)p);
}
__device__ __forceinline__ void sts32(uint32_t addr, uint32_t v) {
    asm volatile("st.shared.b32 [%0], %1;" :: "r"(addr), "r"(v));
}
__device__ __forceinline__ void cpa16(uint32_t dst, const void* src) {
    asm volatile("cp.async.cg.shared.global [%0], [%1], 16;" :: "r"(dst), "l"(src));
}
#define CP_COMMIT() asm volatile("cp.async.commit_group;" ::: "memory")
template <int N>
__device__ __forceinline__ void cp_wait() {
    asm volatile("cp.async.wait_group %0;" :: "n"(N) : "memory");
}
__device__ __forceinline__ void ldmx4(uint32_t r[4], uint32_t addr) {
    asm volatile("ldmatrix.sync.aligned.m8n8.x4.shared.b16 {%0,%1,%2,%3}, [%4];"
                 : "=r"(r[0]), "=r"(r[1]), "=r"(r[2]), "=r"(r[3]) : "r"(addr));
}
__device__ __forceinline__ void mma16816(float d[4], const uint32_t a[4],
                                         const uint32_t b[2]) {
    asm volatile(
        "mma.sync.aligned.m16n8k16.row.col.f32.bf16.bf16.f32 "
        "{%0,%1,%2,%3}, {%4,%5,%6,%7}, {%8,%9}, {%0,%1,%2,%3};"
        : "+f"(d[0]), "+f"(d[1]), "+f"(d[2]), "+f"(d[3])
        : "r"(a[0]), "r"(a[1]), "r"(a[2]), "r"(a[3]), "r"(b[0]), "r"(b[1]));
}
// fast bf16 hi/lo split: 2 CVTs + 2 LOPs + 2 FADDs per pair
__device__ __forceinline__ void fsplit2(float f0, float f1, uint32_t& hw, uint32_t& lw) {
    asm("cvt.rn.bf16x2.f32 %0, %1, %2;" : "=r"(hw) : "f"(f1), "f"(f0));
    float h0 = __uint_as_float(hw << 16);
    float h1 = __uint_as_float(hw & 0xFFFF0000u);
    asm("cvt.rn.bf16x2.f32 %0, %1, %2;" : "=r"(lw) : "f"(f1 - h1), "f"(f0 - h0));
}

// smem: A double-buffered (hi+lo), B double-buffered (hi+lo); rows 144B padded.
#define RS 144
#define ABUF 36864
#define OAH(b) ((b) * ABUF)
#define OAL(b) ((b) * ABUF + 18432)
#define BBASE 73728
#define BBUF 18432
#define OBH(b) (BBASE + (b) * BBUF)
#define OBL(b) (BBASE + (b) * BBUF + 9216)
#define SMEM_DYN 110592
#define LS_STRIDE 66

extern __shared__ char dsm[];

// ---------------------------------------------------------------------------
// k0: split w; zero accumulators.
// ---------------------------------------------------------------------------
__global__ void k0_prep(const float* __restrict__ w) {
    int i = blockIdx.x * 256 + threadIdx.x;
    float f = w[i];
    __nv_bfloat16 h = __float2bfloat16(f);
    g_wh[i] = h;
    g_wl[i] = __float2bfloat16(f - __bfloat162float(h));
    if (i < N_ * K_) g_asum[i] = 0.f;
    if (i < N_)      g_nsum[i] = 0.f;
}

// ---------------------------------------------------------------------------
// B tile stage via cp.async: 64 rows x 64 bf16 from [r*ld + coff].
// ---------------------------------------------------------------------------
__device__ __forceinline__ void stageB(uint32_t BhD, uint32_t BlD,
                                       const __nv_bfloat16* __restrict__ srcH,
                                       const __nv_bfloat16* __restrict__ srcL,
                                       int ld, int coff, int t) {
    int r0 = t >> 3;
    int cc = (t & 7) * 8;
#pragma unroll
    for (int it = 0; it < 4; ++it) {
        int r = it * 16 + r0;
        cpa16(BhD + r * RS + cc * 2, srcH + (size_t)r * ld + coff + cc);
        cpa16(BlD + r * RS + cc * 2, srcL + (size_t)r * ld + coff + cc);
    }
}

// one ks-slice (k=32 of 64-contraction): 3 terms, 18 ldmatrix + 48 HMMA / warp
__device__ __forceinline__ void mma_ks(int ks, uint32_t Ah, uint32_t Al,
                                       uint32_t Bh, uint32_t Bl,
                                       float acc[2][8][4], int w, int lane) {
    int arow = lane & 15;
    int asel = (lane >> 4) * 16;
    int brow = (lane & 7) + ((lane >> 4) << 3);
    int bsel = ((lane >> 3) & 1) * 16;
    int kb = ks * 32;
#pragma unroll
    for (int term = 0; term < 3; ++term) {
        uint32_t Ab = (term == 2) ? Al : Ah;
        uint32_t Bb = (term == 1) ? Bl : Bh;
        uint32_t a[2][4];
#pragma unroll
        for (int mt = 0; mt < 2; ++mt)
            ldmx4(a[mt], Ab + (w * 32 + mt * 16 + arow) * RS + kb + asel);
        uint32_t b[8][2];
#pragma unroll
        for (int p = 0; p < 4; ++p) {
            uint32_t r[4];
            ldmx4(r, Bb + (p * 16 + brow) * RS + kb + bsel);
            b[2 * p][0] = r[0]; b[2 * p][1] = r[1];
            b[2 * p + 1][0] = r[2]; b[2 * p + 1][1] = r[3];
        }
#pragma unroll
        for (int mt = 0; mt < 2; ++mt)
#pragma unroll
            for (int nt = 0; nt < 8; ++nt)
                mma16816(acc[mt][nt], a[mt], b[nt]);
    }
}

__device__ __forceinline__ void store_frags(float* Ls, float acc[2][8][4],
                                            int w, int lane) {
#pragma unroll
    for (int mt = 0; mt < 2; ++mt)
#pragma unroll
        for (int nt = 0; nt < 8; ++nt) {
            int r0 = w * 32 + mt * 16 + (lane >> 2);
            int c = nt * 8 + (lane & 3) * 2;
            Ls[r0 * LS_STRIDE + c]           = acc[mt][nt][0];
            Ls[r0 * LS_STRIDE + c + 1]       = acc[mt][nt][1];
            Ls[(r0 + 8) * LS_STRIDE + c]     = acc[mt][nt][2];
            Ls[(r0 + 8) * LS_STRIDE + c + 1] = acc[mt][nt][3];
        }
}

// ---------------------------------------------------------------------------
// g1: logits D[s=128,k=64] over C (8 chunks of 64). Convert of chunk ch+1 is
// interleaved with MMA of chunk ch (double-buffered A). B via cp.async.
// ---------------------------------------------------------------------------
__global__ void __launch_bounds__(128) g1_logits(const float* __restrict__ x) {
    uint32_t sb = smem_u32(dsm);
    int t = threadIdx.x, w = t >> 5, lane = t & 31;
    int n = blockIdx.y, s0 = blockIdx.x * 128;
    const float* xn = x + (size_t)n * C_ * S_ + s0;

    float acc[2][8][4];
#pragma unroll
    for (int i = 0; i < 2; ++i)
#pragma unroll
        for (int j = 0; j < 8; ++j)
#pragma unroll
            for (int q = 0; q < 4; ++q) acc[i][j][q] = 0.f;
    float sumsq = 0.f;
    float xr[64];

    // prologue: chunk0 -> regs -> A buf0; stage B0, B1; preload chunk1 regs
#pragma unroll
    for (int cp = 0; cp < 64; ++cp) xr[cp] = xn[(size_t)cp * S_ + t];
    stageB(sb + OBH(0), sb + OBL(0), g_wh, g_wl, C_, 0, t);
    CP_COMMIT();
#pragma unroll
    for (int cp = 0; cp < 32; ++cp) {
        float f0 = xr[2 * cp], f1 = xr[2 * cp + 1];
        sumsq += f0 * f0 + f1 * f1;
        uint32_t hw, lw;
        fsplit2(f0, f1, hw, lw);
        sts32(sb + OAH(0) + t * RS + cp * 4, hw);
        sts32(sb + OAL(0) + t * RS + cp * 4, lw);
    }
#pragma unroll
    for (int cp = 0; cp < 64; ++cp) xr[cp] = xn[(size_t)(64 + cp) * S_ + t];
    stageB(sb + OBH(1), sb + OBL(1), g_wh, g_wl, C_, 64, t);
    CP_COMMIT();
    cp_wait<1>();
    __syncthreads();

    for (int ch = 0; ch < 8; ++ch) {
        int cur = ch & 1, nxt = (ch + 1) & 1;
        bool has_cvt = (ch + 1 < 8);
        // fused: MMA(cur) + convert chunk ch+1 into A[nxt]
#pragma unroll
        for (int ks = 0; ks < 4; ++ks) {
            mma_ks(ks, sb + OAH(cur), sb + OAL(cur), sb + OBH(cur), sb + OBL(cur),
                   acc, w, lane);
            if (has_cvt) {
#pragma unroll
                for (int p = 0; p < 8; ++p) {
                    int cp = ks * 8 + p;
                    float f0 = xr[2 * cp], f1 = xr[2 * cp + 1];
                    sumsq += f0 * f0 + f1 * f1;
                    uint32_t hw, lw;
                    fsplit2(f0, f1, hw, lw);
                    sts32(sb + OAH(nxt) + t * RS + cp * 4, hw);
                    sts32(sb + OAL(nxt) + t * RS + cp * 4, lw);
                }
            }
        }
        if (ch + 2 < 8) {
            int cc0 = (ch + 2) * 64;
#pragma unroll
            for (int cp = 0; cp < 64; ++cp) xr[cp] = xn[(size_t)(cc0 + cp) * S_ + t];
        }
        __syncthreads();
        if (ch + 2 < 8) {
            stageB(sb + OBH(cur), sb + OBL(cur), g_wh, g_wl, C_, (ch + 2) * 64, t);
            CP_COMMIT();
            cp_wait<1>();
        } else if (ch + 1 < 8) {
            cp_wait<0>();
        }
        if (ch + 1 < 8) __syncthreads();
    }

    float* Ls = (float*)dsm;
    store_frags(Ls, acc, w, lane);
    __syncthreads();

    // softmax over k for s = s0+t; logits scaled by invnorm(s)
    float inv = 1.f / fmaxf(sqrtf(sumsq), 1e-12f);
    float m = -1e30f;
#pragma unroll
    for (int k = 0; k < K_; ++k) m = fmaxf(m, Ls[t * LS_STRIDE + k] * inv);
    float sum = 0.f;
#pragma unroll
    for (int k = 0; k < K_; ++k) {
        float e = expf(Ls[t * LS_STRIDE + k] * inv - m);
        Ls[t * LS_STRIDE + k] = e;
        sum += e;
    }
    float rs = 1.f / sum;
#pragma unroll
    for (int k = 0; k < K_; ++k) {
        float a = Ls[t * LS_STRIDE + k] * rs;
        Ls[t * LS_STRIDE + k] = a;                   // unscaled (for asum)
        float ap = a * inv;
        __nv_bfloat16 h = __float2bfloat16(ap);
        size_t idx = (((size_t)n * K_ + k) << 10) + s0 + t;
        g_ah[idx] = h;
        g_al[idx] = __float2bfloat16(ap - __bfloat162float(h));
    }
    __syncthreads();
    if (t < K_) {
        float s = 0.f;
#pragma unroll
        for (int si = 0; si < 128; ++si) s += Ls[si * LS_STRIDE + t];
        atomicAdd(&g_asum[n * K_ + t], s);
    }
}

// ---------------------------------------------------------------------------
// g2: vlad D[c=128,k=64] over S (16 chunks of 64). Same fused pipeline.
// ---------------------------------------------------------------------------
__global__ void __launch_bounds__(128) g2_vlad(const float* __restrict__ x) {
    uint32_t sb = smem_u32(dsm);
    int t = threadIdx.x, w = t >> 5, lane = t & 31;
    int n = blockIdx.y, c0 = blockIdx.x * 128;
    const float* xn = x + (size_t)n * C_ * S_;
    const __nv_bfloat16* ahn = g_ah + (size_t)n * K_ * S_;
    const __nv_bfloat16* aln = g_al + (size_t)n * K_ * S_;

    float acc[2][8][4];
#pragma unroll
    for (int i = 0; i < 2; ++i)
#pragma unroll
        for (int j = 0; j < 8; ++j)
#pragma unroll
            for (int q = 0; q < 4; ++q) acc[i][j][q] = 0.f;
    float2 xr[32];

#pragma unroll
    for (int j = 0; j < 32; ++j)
        xr[j] = *(const float2*)&xn[(size_t)(c0 + j * 4 + w) * S_ + lane * 2];
    stageB(sb + OBH(0), sb + OBL(0), ahn, aln, S_, 0, t);
    CP_COMMIT();
#pragma unroll
    for (int j = 0; j < 32; ++j) {
        int c = j * 4 + w;
        uint32_t hw, lw;
        fsplit2(xr[j].x, xr[j].y, hw, lw);
        sts32(sb + OAH(0) + c * RS + lane * 4, hw);
        sts32(sb + OAL(0) + c * RS + lane * 4, lw);
    }
#pragma unroll
    for (int j = 0; j < 32; ++j)
        xr[j] = *(const float2*)&xn[(size_t)(c0 + j * 4 + w) * S_ + 64 + lane * 2];
    stageB(sb + OBH(1), sb + OBL(1), ahn, aln, S_, 64, t);
    CP_COMMIT();
    cp_wait<1>();
    __syncthreads();

    for (int ch = 0; ch < 16; ++ch) {
        int cur = ch & 1, nxt = (ch + 1) & 1;
        bool has_cvt = (ch + 1 < 16);
#pragma unroll
        for (int ks = 0; ks < 4; ++ks) {
            mma_ks(ks, sb + OAH(cur), sb + OAL(cur), sb + OBH(cur), sb + OBL(cur),
                   acc, w, lane);
            if (has_cvt) {
#pragma unroll
                for (int p = 0; p < 8; ++p) {
                    int j = ks * 8 + p;
                    int c = j * 4 + w;
                    uint32_t hw, lw;
                    fsplit2(xr[j].x, xr[j].y, hw, lw);
                    sts32(sb + OAH(nxt) + c * RS + lane * 4, hw);
                    sts32(sb + OAL(nxt) + c * RS + lane * 4, lw);
                }
            }
        }
        if (ch + 2 < 16) {
            int ss0 = (ch + 2) * 64;
#pragma unroll
            for (int j = 0; j < 32; ++j)
                xr[j] = *(const float2*)&xn[(size_t)(c0 + j * 4 + w) * S_ + ss0 + lane * 2];
        }
        __syncthreads();
        if (ch + 2 < 16) {
            stageB(sb + OBH(cur), sb + OBL(cur), ahn, aln, S_, (ch + 2) * 64, t);
            CP_COMMIT();
            cp_wait<1>();
        } else if (ch + 1 < 16) {
            cp_wait<0>();
        }
        if (ch + 1 < 16) __syncthreads();
    }

    float* Ds = (float*)dsm;
    store_frags(Ds, acc, w, lane);
    __syncthreads();

#pragma unroll 4
    for (int k = 0; k < K_; ++k)
        g_vlad[(((size_t)n * K_ + k) << 9) + c0 + t] = Ds[t * LS_STRIDE + k];
}

// ---------------------------------------------------------------------------
// k4: per-(n,k): subtract asum*centroid, intra-normalize, write out, per-n sumsq.
// ---------------------------------------------------------------------------
__global__ void k4_intranorm(const float* __restrict__ centroids,
                             float* __restrict__ out) {
    int nk = blockIdx.x;
    int n = nk >> 6, k = nk & 63;
    int t = threadIdx.x;

    float asum = g_asum[nk];
    float v[4];
    float ss = 0.f;
#pragma unroll
    for (int j = 0; j < 4; ++j) {
        int c = t + j * 128;
        float val = g_vlad[(size_t)nk * C_ + c] - asum * centroids[k * C_ + c];
        v[j] = val;
        ss += val * val;
    }
#pragma unroll
    for (int o = 16; o; o >>= 1) ss += __shfl_xor_sync(0xffffffffu, ss, o);
    __shared__ float red[4];
    if ((t & 31) == 0) red[t >> 5] = ss;
    __syncthreads();
    float total = red[0] + red[1] + red[2] + red[3];

    float invn = 1.f / fmaxf(sqrtf(total), 1e-12f);
    if (t == 0) atomicAdd(&g_nsum[n], total * invn * invn);

#pragma unroll
    for (int j = 0; j < 4; ++j) {
        int c = t + j * 128;
        out[(size_t)n * (K_ * C_) + k * C_ + c] = v[j] * invn;
    }
}

// ---------------------------------------------------------------------------
// k5: global L2 normalization per n.
// ---------------------------------------------------------------------------
__global__ void k5_globalnorm(float* __restrict__ out) {
    int idx = blockIdx.x * 256 + threadIdx.x;
    int n = idx >> 15;
    float g = g_nsum[n];
    out[idx] *= 1.f / fmaxf(sqrtf(g), 1e-12f);
}

// ---------------------------------------------------------------------------
extern "C" void kernel_launch(void* const* d_in, const int* in_sizes, int n_in,
                              void* d_out, int out_size) {
    const float* x    = (const float*)d_in[0];
    const float* w    = (const float*)d_in[1];
    const float* cent = (const float*)d_in[2];
    float* out = (float*)d_out;

    static int smem_set = 0;
    if (!smem_set) {
        cudaFuncSetAttribute(g1_logits, cudaFuncAttributeMaxDynamicSharedMemorySize, SMEM_DYN);
        cudaFuncSetAttribute(g2_vlad,   cudaFuncAttributeMaxDynamicSharedMemorySize, SMEM_DYN);
        smem_set = 1;
    }

    k0_prep<<<(K_ * C_) / 256, 256>>>(w);
    g1_logits<<<dim3(S_ / 128, N_), 128, SMEM_DYN>>>(x);
    g2_vlad<<<dim3(C_ / 128, N_), 128, SMEM_DYN>>>(x);
    k4_intranorm<<<N_ * K_, 128>>>(cent, out);
    k5_globalnorm<<<(N_ * K_ * C_) / 256, 256>>>(out);
}

// round 7
// speedup vs baseline: 3.7095x; 1.5591x over previous
#include <cuda_runtime.h>
#include <cuda_fp16.h>
#include <math.h>
#include <stdint.h>

#define N_ 64
#define C_ 512
#define S_ 1024
#define K_ 64

// ---- scratch (device globals; allocation-free) ------------------------------
__device__ __half g_wh[K_ * C_];          // w as fp16
__device__ __half g_ah[N_ * K_ * S_];     // a' = softmax*invnorm, fp16
__device__ float g_asum[N_ * K_];
__device__ float g_vlad[N_ * K_ * C_];
__device__ float g_nsum[N_];

// ---- helpers ----------------------------------------------------------------
__device__ __forceinline__ uint32_t smem_u32(const void* p) {
    return (uint32_t)__cvta_generic_to_shared((void*)p);
}
__device__ __forceinline__ void sts32(uint32_t addr, uint32_t v) {
    asm volatile("st.shared.b32 [%0], %1;" :: "r"(addr), "r"(v));
}
__device__ __forceinline__ void cpa16(uint32_t dst, const void* src) {
    asm volatile("cp.async.cg.shared.global [%0], [%1], 16;" :: "r"(dst), "l"(src));
}
#define CP_COMMIT() asm volatile("cp.async.commit_group;" ::: "memory")
template <int N>
__device__ __forceinline__ void cp_wait() {
    asm volatile("cp.async.wait_group %0;" :: "n"(N) : "memory");
}
__device__ __forceinline__ void ldmx4(uint32_t r[4], uint32_t addr) {
    asm volatile("ldmatrix.sync.aligned.m8n8.x4.shared.b16 {%0,%1,%2,%3}, [%4];"
                 : "=r"(r[0]), "=r"(r[1]), "=r"(r[2]), "=r"(r[3]) : "r"(addr));
}
__device__ __forceinline__ void mma16816(float d[4], const uint32_t a[4],
                                         const uint32_t b[2]) {
    asm volatile(
        "mma.sync.aligned.m16n8k16.row.col.f32.f16.f16.f32 "
        "{%0,%1,%2,%3}, {%4,%5,%6,%7}, {%8,%9}, {%0,%1,%2,%3};"
        : "+f"(d[0]), "+f"(d[1]), "+f"(d[2]), "+f"(d[3])
        : "r"(a[0]), "r"(a[1]), "r"(a[2]), "r"(a[3]), "r"(b[0]), "r"(b[1]));
}
// pack two fp32 -> fp16x2 (lo = f0, hi = f1)
__device__ __forceinline__ uint32_t cvt2h(float f0, float f1) {
    uint32_t r;
    asm("cvt.rn.f16x2.f32 %0, %1, %2;" : "=r"(r) : "f"(f1), "f"(f0));
    return r;
}

// smem: A double-buffered, B double-buffered; rows 144B padded (64 fp16 + pad).
#define RS 144
#define OA(b) ((b) * 18432)
#define OB(b) (36864 + (b) * 9216)
#define SMEM_DYN 55296
#define LS_STRIDE 66

extern __shared__ char dsm[];

// ---------------------------------------------------------------------------
// k0: w -> fp16; zero accumulators.
// ---------------------------------------------------------------------------
__global__ void k0_prep(const float* __restrict__ w) {
    int i = blockIdx.x * 256 + threadIdx.x;
    g_wh[i] = __float2half(w[i]);
    if (i < N_ * K_) g_asum[i] = 0.f;
    if (i < N_)      g_nsum[i] = 0.f;
}

// ---------------------------------------------------------------------------
// B tile stage via cp.async: 64 rows x 64 fp16 from [r*ld + coff]. 4 cp/thread.
// ---------------------------------------------------------------------------
__device__ __forceinline__ void stageB(uint32_t Bd,
                                       const __half* __restrict__ src,
                                       int ld, int coff, int t) {
    int r0 = t >> 3;
    int cc = (t & 7) * 8;
#pragma unroll
    for (int it = 0; it < 4; ++it) {
        int r = it * 16 + r0;
        cpa16(Bd + r * RS + cc * 2, src + (size_t)r * ld + coff + cc);
    }
}

// one ks-slice (k=32 of 64): 6 ldmatrix + 16 HMMA per warp (single term fp16)
__device__ __forceinline__ void mma_ks(int ks, uint32_t A, uint32_t B,
                                       float acc[2][8][4], int w, int lane) {
    int arow = lane & 15;
    int asel = (lane >> 4) * 16;
    int brow = (lane & 7) + ((lane >> 4) << 3);
    int bsel = ((lane >> 3) & 1) * 16;
    int kb = ks * 32;
    uint32_t a[2][4];
#pragma unroll
    for (int mt = 0; mt < 2; ++mt)
        ldmx4(a[mt], A + (w * 32 + mt * 16 + arow) * RS + kb + asel);
    uint32_t b[8][2];
#pragma unroll
    for (int p = 0; p < 4; ++p) {
        uint32_t r[4];
        ldmx4(r, B + (p * 16 + brow) * RS + kb + bsel);
        b[2 * p][0] = r[0]; b[2 * p][1] = r[1];
        b[2 * p + 1][0] = r[2]; b[2 * p + 1][1] = r[3];
    }
#pragma unroll
    for (int mt = 0; mt < 2; ++mt)
#pragma unroll
        for (int nt = 0; nt < 8; ++nt)
            mma16816(acc[mt][nt], a[mt], b[nt]);
}

__device__ __forceinline__ void store_frags(float* Ls, float acc[2][8][4],
                                            int w, int lane) {
#pragma unroll
    for (int mt = 0; mt < 2; ++mt)
#pragma unroll
        for (int nt = 0; nt < 8; ++nt) {
            int r0 = w * 32 + mt * 16 + (lane >> 2);
            int c = nt * 8 + (lane & 3) * 2;
            Ls[r0 * LS_STRIDE + c]           = acc[mt][nt][0];
            Ls[r0 * LS_STRIDE + c + 1]       = acc[mt][nt][1];
            Ls[(r0 + 8) * LS_STRIDE + c]     = acc[mt][nt][2];
            Ls[(r0 + 8) * LS_STRIDE + c + 1] = acc[mt][nt][3];
        }
}

// ---------------------------------------------------------------------------
// g1: logits D[s=128,k=64] over C (8 chunks of 64). fp16 single-term.
// Epilogue: invnorm scale + softmax over k; write a' fp16 + asum.
// ---------------------------------------------------------------------------
__global__ void __launch_bounds__(128) g1_logits(const float* __restrict__ x) {
    uint32_t sb = smem_u32(dsm);
    int t = threadIdx.x, w = t >> 5, lane = t & 31;
    int n = blockIdx.y, s0 = blockIdx.x * 128;
    const float* xn = x + (size_t)n * C_ * S_ + s0;

    float acc[2][8][4];
#pragma unroll
    for (int i = 0; i < 2; ++i)
#pragma unroll
        for (int j = 0; j < 8; ++j)
#pragma unroll
            for (int q = 0; q < 4; ++q) acc[i][j][q] = 0.f;
    float sumsq = 0.f;
    float xr[64];

    // prologue
#pragma unroll
    for (int cp = 0; cp < 64; ++cp) xr[cp] = xn[(size_t)cp * S_ + t];
    stageB(sb + OB(0), g_wh, C_, 0, t);
    CP_COMMIT();
#pragma unroll
    for (int cp = 0; cp < 32; ++cp) {
        float f0 = xr[2 * cp], f1 = xr[2 * cp + 1];
        sumsq += f0 * f0 + f1 * f1;
        sts32(sb + OA(0) + t * RS + cp * 4, cvt2h(f0, f1));
    }
#pragma unroll
    for (int cp = 0; cp < 64; ++cp) xr[cp] = xn[(size_t)(64 + cp) * S_ + t];
    stageB(sb + OB(1), g_wh, C_, 64, t);
    CP_COMMIT();
    cp_wait<1>();
    __syncthreads();

    for (int ch = 0; ch < 8; ++ch) {
        int cur = ch & 1, nxt = (ch + 1) & 1;
        bool has_cvt = (ch + 1 < 8);
#pragma unroll
        for (int ks = 0; ks < 4; ++ks) {
            mma_ks(ks, sb + OA(cur), sb + OB(cur), acc, w, lane);
            if (has_cvt) {
#pragma unroll
                for (int p = 0; p < 8; ++p) {
                    int cp = ks * 8 + p;
                    float f0 = xr[2 * cp], f1 = xr[2 * cp + 1];
                    sumsq += f0 * f0 + f1 * f1;
                    sts32(sb + OA(nxt) + t * RS + cp * 4, cvt2h(f0, f1));
                }
            }
        }
        if (ch + 2 < 8) {
            int cc0 = (ch + 2) * 64;
#pragma unroll
            for (int cp = 0; cp < 64; ++cp) xr[cp] = xn[(size_t)(cc0 + cp) * S_ + t];
        }
        __syncthreads();
        if (ch + 2 < 8) {
            stageB(sb + OB(cur), g_wh, C_, (ch + 2) * 64, t);
            CP_COMMIT();
            cp_wait<1>();
        } else if (ch + 1 < 8) {
            cp_wait<0>();
        }
        if (ch + 1 < 8) __syncthreads();
    }

    float* Ls = (float*)dsm;
    store_frags(Ls, acc, w, lane);
    __syncthreads();

    // softmax over k for s = s0+t; logits scaled by invnorm(s)
    float inv = 1.f / fmaxf(sqrtf(sumsq), 1e-12f);
    float m = -1e30f;
#pragma unroll
    for (int k = 0; k < K_; ++k) m = fmaxf(m, Ls[t * LS_STRIDE + k] * inv);
    float sum = 0.f;
#pragma unroll
    for (int k = 0; k < K_; ++k) {
        float e = expf(Ls[t * LS_STRIDE + k] * inv - m);
        Ls[t * LS_STRIDE + k] = e;
        sum += e;
    }
    float rs = 1.f / sum;
#pragma unroll
    for (int k = 0; k < K_; ++k) {
        float a = Ls[t * LS_STRIDE + k] * rs;
        Ls[t * LS_STRIDE + k] = a;                   // unscaled (for asum)
        g_ah[(((size_t)n * K_ + k) << 10) + s0 + t] = __float2half(a * inv);
    }
    __syncthreads();
    if (t < K_) {
        float s = 0.f;
#pragma unroll
        for (int si = 0; si < 128; ++si) s += Ls[si * LS_STRIDE + t];
        atomicAdd(&g_asum[n * K_ + t], s);
    }
}

// ---------------------------------------------------------------------------
// g2: vlad D[c=128,k=64] over S (16 chunks of 64). fp16 single-term.
// ---------------------------------------------------------------------------
__global__ void __launch_bounds__(128) g2_vlad(const float* __restrict__ x) {
    uint32_t sb = smem_u32(dsm);
    int t = threadIdx.x, w = t >> 5, lane = t & 31;
    int n = blockIdx.y, c0 = blockIdx.x * 128;
    const float* xn = x + (size_t)n * C_ * S_;
    const __half* ahn = g_ah + (size_t)n * K_ * S_;

    float acc[2][8][4];
#pragma unroll
    for (int i = 0; i < 2; ++i)
#pragma unroll
        for (int j = 0; j < 8; ++j)
#pragma unroll
            for (int q = 0; q < 4; ++q) acc[i][j][q] = 0.f;
    float2 xr[32];

#pragma unroll
    for (int j = 0; j < 32; ++j)
        xr[j] = *(const float2*)&xn[(size_t)(c0 + j * 4 + w) * S_ + lane * 2];
    stageB(sb + OB(0), ahn, S_, 0, t);
    CP_COMMIT();
#pragma unroll
    for (int j = 0; j < 32; ++j) {
        int c = j * 4 + w;
        sts32(sb + OA(0) + c * RS + lane * 4, cvt2h(xr[j].x, xr[j].y));
    }
#pragma unroll
    for (int j = 0; j < 32; ++j)
        xr[j] = *(const float2*)&xn[(size_t)(c0 + j * 4 + w) * S_ + 64 + lane * 2];
    stageB(sb + OB(1), ahn, S_, 64, t);
    CP_COMMIT();
    cp_wait<1>();
    __syncthreads();

    for (int ch = 0; ch < 16; ++ch) {
        int cur = ch & 1, nxt = (ch + 1) & 1;
        bool has_cvt = (ch + 1 < 16);
#pragma unroll
        for (int ks = 0; ks < 4; ++ks) {
            mma_ks(ks, sb + OA(cur), sb + OB(cur), acc, w, lane);
            if (has_cvt) {
#pragma unroll
                for (int p = 0; p < 8; ++p) {
                    int j = ks * 8 + p;
                    int c = j * 4 + w;
                    sts32(sb + OA(nxt) + c * RS + lane * 4, cvt2h(xr[j].x, xr[j].y));
                }
            }
        }
        if (ch + 2 < 16) {
            int ss0 = (ch + 2) * 64;
#pragma unroll
            for (int j = 0; j < 32; ++j)
                xr[j] = *(const float2*)&xn[(size_t)(c0 + j * 4 + w) * S_ + ss0 + lane * 2];
        }
        __syncthreads();
        if (ch + 2 < 16) {
            stageB(sb + OB(cur), ahn, S_, (ch + 2) * 64, t);
            CP_COMMIT();
            cp_wait<1>();
        } else if (ch + 1 < 16) {
            cp_wait<0>();
        }
        if (ch + 1 < 16) __syncthreads();
    }

    float* Ds = (float*)dsm;
    store_frags(Ds, acc, w, lane);
    __syncthreads();

#pragma unroll 4
    for (int k = 0; k < K_; ++k)
        g_vlad[(((size_t)n * K_ + k) << 9) + c0 + t] = Ds[t * LS_STRIDE + k];
}

// ---------------------------------------------------------------------------
// k4: per-(n,k): subtract asum*centroid, intra-normalize, write out, per-n sumsq.
// ---------------------------------------------------------------------------
__global__ void k4_intranorm(const float* __restrict__ centroids,
                             float* __restrict__ out) {
    int nk = blockIdx.x;
    int n = nk >> 6, k = nk & 63;
    int t = threadIdx.x;

    float asum = g_asum[nk];
    float v[4];
    float ss = 0.f;
#pragma unroll
    for (int j = 0; j < 4; ++j) {
        int c = t + j * 128;
        float val = g_vlad[(size_t)nk * C_ + c] - asum * centroids[k * C_ + c];
        v[j] = val;
        ss += val * val;
    }
#pragma unroll
    for (int o = 16; o; o >>= 1) ss += __shfl_xor_sync(0xffffffffu, ss, o);
    __shared__ float red[4];
    if ((t & 31) == 0) red[t >> 5] = ss;
    __syncthreads();
    float total = red[0] + red[1] + red[2] + red[3];

    float invn = 1.f / fmaxf(sqrtf(total), 1e-12f);
    if (t == 0) atomicAdd(&g_nsum[n], total * invn * invn);

#pragma unroll
    for (int j = 0; j < 4; ++j) {
        int c = t + j * 128;
        out[(size_t)n * (K_ * C_) + k * C_ + c] = v[j] * invn;
    }
}

// ---------------------------------------------------------------------------
// k5: global L2 normalization per n.
// ---------------------------------------------------------------------------
__global__ void k5_globalnorm(float* __restrict__ out) {
    int idx = blockIdx.x * 256 + threadIdx.x;
    int n = idx >> 15;
    float g = g_nsum[n];
    out[idx] *= 1.f / fmaxf(sqrtf(g), 1e-12f);
}

// ---------------------------------------------------------------------------
extern "C" void kernel_launch(void* const* d_in, const int* in_sizes, int n_in,
                              void* d_out, int out_size) {
    const float* x    = (const float*)d_in[0];
    const float* w    = (const float*)d_in[1];
    const float* cent = (const float*)d_in[2];
    float* out = (float*)d_out;

    static int smem_set = 0;
    if (!smem_set) {
        cudaFuncSetAttribute(g1_logits, cudaFuncAttributeMaxDynamicSharedMemorySize, SMEM_DYN);
        cudaFuncSetAttribute(g2_vlad,   cudaFuncAttributeMaxDynamicSharedMemorySize, SMEM_DYN);
        smem_set = 1;
    }

    k0_prep<<<(K_ * C_) / 256, 256>>>(w);
    g1_logits<<<dim3(S_ / 128, N_), 128, SMEM_DYN>>>(x);
    g2_vlad<<<dim3(C_ / 128, N_), 128, SMEM_DYN>>>(x);
    k4_intranorm<<<N_ * K_, 128>>>(cent, out);
    k5_globalnorm<<<(N_ * K_ * C_) / 256, 256>>>(out);
}

// round 10
// speedup vs baseline: 4.1274x; 1.1127x over previous
#include <cuda_runtime.h>
#include <cuda_fp16.h>
#include <math.h>
#include <stdint.h>

#define N_ 64
#define C_ 512
#define S_ 1024
#define K_ 64

// ---- scratch (device globals; allocation-free) ------------------------------
__device__ __half g_wh[K_ * C_];          // w as fp16
__device__ __half g_ah[N_ * K_ * S_];     // a' = softmax*invnorm, fp16
__device__ float g_asum[N_ * K_];
__device__ float g_vlad[N_ * K_ * C_];

// ---- helpers ----------------------------------------------------------------
__device__ __forceinline__ uint32_t smem_u32(const void* p) {
    return (uint32_t)__cvta_generic_to_shared((void*)p);
}
__device__ __forceinline__ void sts32(uint32_t addr, uint32_t v) {
    asm volatile("st.shared.b32 [%0], %1;" :: "r"(addr), "r"(v));
}
__device__ __forceinline__ void cpa16(uint32_t dst, const void* src) {
    asm volatile("cp.async.cg.shared.global [%0], [%1], 16;" :: "r"(dst), "l"(src));
}
#define CP_COMMIT() asm volatile("cp.async.commit_group;" ::: "memory")
template <int N>
__device__ __forceinline__ void cp_wait() {
    asm volatile("cp.async.wait_group %0;" :: "n"(N) : "memory");
}
__device__ __forceinline__ void ldmx4(uint32_t r[4], uint32_t addr) {
    asm volatile("ldmatrix.sync.aligned.m8n8.x4.shared.b16 {%0,%1,%2,%3}, [%4];"
                 : "=r"(r[0]), "=r"(r[1]), "=r"(r[2]), "=r"(r[3]) : "r"(addr));
}
__device__ __forceinline__ void mma16816(float d[4], const uint32_t a[4],
                                         const uint32_t b[2]) {
    asm volatile(
        "mma.sync.aligned.m16n8k16.row.col.f32.f16.f16.f32 "
        "{%0,%1,%2,%3}, {%4,%5,%6,%7}, {%8,%9}, {%0,%1,%2,%3};"
        : "+f"(d[0]), "+f"(d[1]), "+f"(d[2]), "+f"(d[3])
        : "r"(a[0]), "r"(a[1]), "r"(a[2]), "r"(a[3]), "r"(b[0]), "r"(b[1]));
}
// pack two fp32 -> fp16x2 (lo = f0, hi = f1)
__device__ __forceinline__ uint32_t cvt2h(float f0, float f1) {
    uint32_t r;
    asm("cvt.rn.f16x2.f32 %0, %1, %2;" : "=r"(r) : "f"(f1), "f"(f0));
    return r;
}

// smem: A double-buffered, B double-buffered; rows 144B padded (64 fp16 + pad).
#define RS 144
#define OA(b) ((b) * 18432)
#define OB(b) (36864 + (b) * 9216)
#define SMEM_DYN 55296
#define LS_STRIDE 66

extern __shared__ char dsm[];

// ---------------------------------------------------------------------------
// k0: w -> fp16; zero asum.
// ---------------------------------------------------------------------------
__global__ void k0_prep(const float* __restrict__ w) {
    int i = blockIdx.x * 256 + threadIdx.x;
    g_wh[i] = __float2half(w[i]);
    if (i < N_ * K_) g_asum[i] = 0.f;
}

// ---------------------------------------------------------------------------
// B tile stage via cp.async: 64 rows x 64 fp16 from [r*ld + coff]. 4 cp/thread.
// ---------------------------------------------------------------------------
__device__ __forceinline__ void stageB(uint32_t Bd,
                                       const __half* __restrict__ src,
                                       int ld, int coff, int t) {
    int r0 = t >> 3;
    int cc = (t & 7) * 8;
#pragma unroll
    for (int it = 0; it < 4; ++it) {
        int r = it * 16 + r0;
        cpa16(Bd + r * RS + cc * 2, src + (size_t)r * ld + coff + cc);
    }
}

// one ks-slice (k=32 of 64): 6 ldmatrix + 16 HMMA per warp (single term fp16)
__device__ __forceinline__ void mma_ks(int ks, uint32_t A, uint32_t B,
                                       float acc[2][8][4], int w, int lane) {
    int arow = lane & 15;
    int asel = (lane >> 4) * 16;
    int brow = (lane & 7) + ((lane >> 4) << 3);
    int bsel = ((lane >> 3) & 1) * 16;
    int kb = ks * 32;
    uint32_t a[2][4];
#pragma unroll
    for (int mt = 0; mt < 2; ++mt)
        ldmx4(a[mt], A + (w * 32 + mt * 16 + arow) * RS + kb + asel);
    uint32_t b[8][2];
#pragma unroll
    for (int p = 0; p < 4; ++p) {
        uint32_t r[4];
        ldmx4(r, B + (p * 16 + brow) * RS + kb + bsel);
        b[2 * p][0] = r[0]; b[2 * p][1] = r[1];
        b[2 * p + 1][0] = r[2]; b[2 * p + 1][1] = r[3];
    }
#pragma unroll
    for (int mt = 0; mt < 2; ++mt)
#pragma unroll
        for (int nt = 0; nt < 8; ++nt)
            mma16816(acc[mt][nt], a[mt], b[nt]);
}

__device__ __forceinline__ void store_frags(float* Ls, float acc[2][8][4],
                                            int w, int lane) {
#pragma unroll
    for (int mt = 0; mt < 2; ++mt)
#pragma unroll
        for (int nt = 0; nt < 8; ++nt) {
            int r0 = w * 32 + mt * 16 + (lane >> 2);
            int c = nt * 8 + (lane & 3) * 2;
            Ls[r0 * LS_STRIDE + c]           = acc[mt][nt][0];
            Ls[r0 * LS_STRIDE + c + 1]       = acc[mt][nt][1];
            Ls[(r0 + 8) * LS_STRIDE + c]     = acc[mt][nt][2];
            Ls[(r0 + 8) * LS_STRIDE + c + 1] = acc[mt][nt][3];
        }
}

// ---------------------------------------------------------------------------
// g1: logits D[s=128,k=64] over C (8 chunks of 64). fp16 single-term.
// Epilogue: invnorm scale + softmax over k; write a' fp16 + asum.
// (round-7 proven structure; + sync before epilogue staging)
// ---------------------------------------------------------------------------
__global__ void __launch_bounds__(128) g1_logits(const float* __restrict__ x) {
    uint32_t sb = smem_u32(dsm);
    int t = threadIdx.x, w = t >> 5, lane = t & 31;
    int n = blockIdx.y, s0 = blockIdx.x * 128;
    const float* xn = x + (size_t)n * C_ * S_ + s0;

    float acc[2][8][4];
#pragma unroll
    for (int i = 0; i < 2; ++i)
#pragma unroll
        for (int j = 0; j < 8; ++j)
#pragma unroll
            for (int q = 0; q < 4; ++q) acc[i][j][q] = 0.f;
    float sumsq = 0.f;
    float xr[64];

    // prologue
#pragma unroll
    for (int cp = 0; cp < 64; ++cp) xr[cp] = xn[(size_t)cp * S_ + t];
    stageB(sb + OB(0), g_wh, C_, 0, t);
    CP_COMMIT();
#pragma unroll
    for (int cp = 0; cp < 32; ++cp) {
        float f0 = xr[2 * cp], f1 = xr[2 * cp + 1];
        sumsq += f0 * f0 + f1 * f1;
        sts32(sb + OA(0) + t * RS + cp * 4, cvt2h(f0, f1));
    }
#pragma unroll
    for (int cp = 0; cp < 64; ++cp) xr[cp] = xn[(size_t)(64 + cp) * S_ + t];
    stageB(sb + OB(1), g_wh, C_, 64, t);
    CP_COMMIT();
    cp_wait<1>();
    __syncthreads();

    for (int ch = 0; ch < 8; ++ch) {
        int cur = ch & 1, nxt = (ch + 1) & 1;
        bool has_cvt = (ch + 1 < 8);
#pragma unroll
        for (int ks = 0; ks < 4; ++ks) {
            mma_ks(ks, sb + OA(cur), sb + OB(cur), acc, w, lane);
            if (has_cvt) {
#pragma unroll
                for (int p = 0; p < 8; ++p) {
                    int cp = ks * 8 + p;
                    float f0 = xr[2 * cp], f1 = xr[2 * cp + 1];
                    sumsq += f0 * f0 + f1 * f1;
                    sts32(sb + OA(nxt) + t * RS + cp * 4, cvt2h(f0, f1));
                }
            }
        }
        if (ch + 2 < 8) {
            int cc0 = (ch + 2) * 64;
#pragma unroll
            for (int cp = 0; cp < 64; ++cp) xr[cp] = xn[(size_t)(cc0 + cp) * S_ + t];
        }
        __syncthreads();
        if (ch + 2 < 8) {
            stageB(sb + OB(cur), g_wh, C_, (ch + 2) * 64, t);
            CP_COMMIT();
            cp_wait<1>();
        } else if (ch + 1 < 8) {
            cp_wait<0>();
        }
        if (ch + 1 < 8) __syncthreads();
    }

    // all warps done with tiles before epilogue staging overwrites smem
    __syncthreads();

    float* Ls = (float*)dsm;
    store_frags(Ls, acc, w, lane);
    __syncthreads();

    // softmax over k for s = s0+t; logits scaled by invnorm(s)
    float inv = 1.f / fmaxf(sqrtf(sumsq), 1e-12f);
    float m = -1e30f;
#pragma unroll
    for (int k = 0; k < K_; ++k) m = fmaxf(m, Ls[t * LS_STRIDE + k] * inv);
    float sum = 0.f;
#pragma unroll
    for (int k = 0; k < K_; ++k) {
        float e = expf(Ls[t * LS_STRIDE + k] * inv - m);
        Ls[t * LS_STRIDE + k] = e;
        sum += e;
    }
    float rs = 1.f / sum;
#pragma unroll
    for (int k = 0; k < K_; ++k) {
        float a = Ls[t * LS_STRIDE + k] * rs;
        Ls[t * LS_STRIDE + k] = a;                   // unscaled (for asum)
        g_ah[(((size_t)n * K_ + k) << 10) + s0 + t] = __float2half(a * inv);
    }
    __syncthreads();
    if (t < K_) {
        float s = 0.f;
#pragma unroll
        for (int si = 0; si < 128; ++si) s += Ls[si * LS_STRIDE + t];
        atomicAdd(&g_asum[n * K_ + t], s);
    }
}

// ---------------------------------------------------------------------------
// g2: vlad D[c=128,k=64] over S (16 chunks of 64). fp16 single-term.
// (round-7 proven structure; + sync before epilogue staging)
// ---------------------------------------------------------------------------
__global__ void __launch_bounds__(128) g2_vlad(const float* __restrict__ x) {
    uint32_t sb = smem_u32(dsm);
    int t = threadIdx.x, w = t >> 5, lane = t & 31;
    int n = blockIdx.y, c0 = blockIdx.x * 128;
    const float* xn = x + (size_t)n * C_ * S_;
    const __half* ahn = g_ah + (size_t)n * K_ * S_;

    float acc[2][8][4];
#pragma unroll
    for (int i = 0; i < 2; ++i)
#pragma unroll
        for (int j = 0; j < 8; ++j)
#pragma unroll
            for (int q = 0; q < 4; ++q) acc[i][j][q] = 0.f;
    float2 xr[32];

#pragma unroll
    for (int j = 0; j < 32; ++j)
        xr[j] = *(const float2*)&xn[(size_t)(c0 + j * 4 + w) * S_ + lane * 2];
    stageB(sb + OB(0), ahn, S_, 0, t);
    CP_COMMIT();
#pragma unroll
    for (int j = 0; j < 32; ++j) {
        int c = j * 4 + w;
        sts32(sb + OA(0) + c * RS + lane * 4, cvt2h(xr[j].x, xr[j].y));
    }
#pragma unroll
    for (int j = 0; j < 32; ++j)
        xr[j] = *(const float2*)&xn[(size_t)(c0 + j * 4 + w) * S_ + 64 + lane * 2];
    stageB(sb + OB(1), ahn, S_, 64, t);
    CP_COMMIT();
    cp_wait<1>();
    __syncthreads();

    for (int ch = 0; ch < 16; ++ch) {
        int cur = ch & 1, nxt = (ch + 1) & 1;
        bool has_cvt = (ch + 1 < 16);
#pragma unroll
        for (int ks = 0; ks < 4; ++ks) {
            mma_ks(ks, sb + OA(cur), sb + OB(cur), acc, w, lane);
            if (has_cvt) {
#pragma unroll
                for (int p = 0; p < 8; ++p) {
                    int j = ks * 8 + p;
                    int c = j * 4 + w;
                    sts32(sb + OA(nxt) + c * RS + lane * 4, cvt2h(xr[j].x, xr[j].y));
                }
            }
        }
        if (ch + 2 < 16) {
            int ss0 = (ch + 2) * 64;
#pragma unroll
            for (int j = 0; j < 32; ++j)
                xr[j] = *(const float2*)&xn[(size_t)(c0 + j * 4 + w) * S_ + ss0 + lane * 2];
        }
        __syncthreads();
        if (ch + 2 < 16) {
            stageB(sb + OB(cur), ahn, S_, (ch + 2) * 64, t);
            CP_COMMIT();
            cp_wait<1>();
        } else if (ch + 1 < 16) {
            cp_wait<0>();
        }
        if (ch + 1 < 16) __syncthreads();
    }

    // all warps done with tiles before epilogue staging overwrites smem
    __syncthreads();

    float* Ds = (float*)dsm;
    store_frags(Ds, acc, w, lane);
    __syncthreads();

#pragma unroll 4
    for (int k = 0; k < K_; ++k)
        g_vlad[(((size_t)n * K_ + k) << 9) + c0 + t] = Ds[t * LS_STRIDE + k];
}

// ---------------------------------------------------------------------------
// k4: per-(n,k): val = vlad - asum*centroid; intra-normalize. Global norm is
// EXACTLY 8 (unit rows after intra-norm), so fold 1/8 and write out directly.
// ---------------------------------------------------------------------------
__global__ void k4_intranorm(const float* __restrict__ centroids,
                             float* __restrict__ out) {
    int nk = blockIdx.x;
    int k = nk & 63;
    int t = threadIdx.x;

    float asum = g_asum[nk];
    float4 vv = ((const float4*)(g_vlad + (size_t)nk * C_))[t];
    float4 cc = ((const float4*)(centroids + (size_t)k * C_))[t];
    float4 val;
    val.x = vv.x - asum * cc.x;
    val.y = vv.y - asum * cc.y;
    val.z = vv.z - asum * cc.z;
    val.w = vv.w - asum * cc.w;
    float ss = val.x * val.x + val.y * val.y + val.z * val.z + val.w * val.w;
#pragma unroll
    for (int o = 16; o; o >>= 1) ss += __shfl_xor_sync(0xffffffffu, ss, o);
    __shared__ float red[4];
    if ((t & 31) == 0) red[t >> 5] = ss;
    __syncthreads();
    float total = red[0] + red[1] + red[2] + red[3];

    float invn = 0.125f / fmaxf(sqrtf(total), 1e-12f);
    val.x *= invn; val.y *= invn; val.z *= invn; val.w *= invn;
    ((float4*)(out + (size_t)nk * C_))[t] = val;
}

// ---------------------------------------------------------------------------
extern "C" void kernel_launch(void* const* d_in, const int* in_sizes, int n_in,
                              void* d_out, int out_size) {
    const float* x    = (const float*)d_in[0];
    const float* w    = (const float*)d_in[1];
    const float* cent = (const float*)d_in[2];
    float* out = (float*)d_out;

    cudaFuncSetAttribute(g1_logits, cudaFuncAttributeMaxDynamicSharedMemorySize, SMEM_DYN);
    cudaFuncSetAttribute(g2_vlad,   cudaFuncAttributeMaxDynamicSharedMemorySize, SMEM_DYN);

    k0_prep<<<(K_ * C_) / 256, 256>>>(w);
    g1_logits<<<dim3(S_ / 128, N_), 128, SMEM_DYN>>>(x);
    g2_vlad<<<dim3(C_ / 128, N_), 128, SMEM_DYN>>>(x);
    k4_intranorm<<<N_ * K_, 128>>>(cent, out);
}

// round 11
// speedup vs baseline: 4.4244x; 1.0719x over previous
#include <cuda_runtime.h>
#include <cuda_fp16.h>
#include <math.h>
#include <stdint.h>

#define N_ 64
#define C_ 512
#define S_ 1024
#define K_ 64

// ---- scratch (device globals; allocation-free) ------------------------------
__device__ __half g_wh[K_ * C_];          // w as fp16
__device__ __half g_ah[N_ * K_ * S_];     // a' = softmax*invnorm, fp16
__device__ float g_asum[N_ * K_];
__device__ float g_vlad[N_ * K_ * C_];

// ---- helpers ----------------------------------------------------------------
__device__ __forceinline__ uint32_t smem_u32(const void* p) {
    return (uint32_t)__cvta_generic_to_shared((void*)p);
}
__device__ __forceinline__ void sts64(uint32_t addr, uint32_t v0, uint32_t v1) {
    asm volatile("st.shared.v2.b32 [%0], {%1, %2};" :: "r"(addr), "r"(v0), "r"(v1));
}
__device__ __forceinline__ void sts128(uint32_t addr, uint32_t v0, uint32_t v1,
                                       uint32_t v2, uint32_t v3) {
    asm volatile("st.shared.v4.b32 [%0], {%1, %2, %3, %4};"
                 :: "r"(addr), "r"(v0), "r"(v1), "r"(v2), "r"(v3));
}
__device__ __forceinline__ void cpa16(uint32_t dst, const void* src) {
    asm volatile("cp.async.cg.shared.global [%0], [%1], 16;" :: "r"(dst), "l"(src));
}
#define CP_COMMIT() asm volatile("cp.async.commit_group;" ::: "memory")
template <int N>
__device__ __forceinline__ void cp_wait() {
    asm volatile("cp.async.wait_group %0;" :: "n"(N) : "memory");
}
__device__ __forceinline__ void ldmx4(uint32_t r[4], uint32_t addr) {
    asm volatile("ldmatrix.sync.aligned.m8n8.x4.shared.b16 {%0,%1,%2,%3}, [%4];"
                 : "=r"(r[0]), "=r"(r[1]), "=r"(r[2]), "=r"(r[3]) : "r"(addr));
}
__device__ __forceinline__ void mma16816(float d[4], const uint32_t a[4],
                                         const uint32_t b[2]) {
    asm volatile(
        "mma.sync.aligned.m16n8k16.row.col.f32.f16.f16.f32 "
        "{%0,%1,%2,%3}, {%4,%5,%6,%7}, {%8,%9}, {%0,%1,%2,%3};"
        : "+f"(d[0]), "+f"(d[1]), "+f"(d[2]), "+f"(d[3])
        : "r"(a[0]), "r"(a[1]), "r"(a[2]), "r"(a[3]), "r"(b[0]), "r"(b[1]));
}
// pack two fp32 -> fp16x2 (lo = f0, hi = f1)
__device__ __forceinline__ uint32_t cvt2h(float f0, float f1) {
    uint32_t r;
    asm("cvt.rn.f16x2.f32 %0, %1, %2;" : "=r"(r) : "f"(f1), "f"(f0));
    return r;
}

// smem: A double-buffered, B double-buffered; rows 144B padded (64 fp16 + pad).
#define RS 144
#define OA(b) ((b) * 18432)
#define OB(b) (36864 + (b) * 9216)
#define G1_SSQ 53248          // 256 floats (2 c-half partials x 128 s)
#define SMEM_DYN 55296
#define LS_STRIDE 66

extern __shared__ char dsm[];

// ---------------------------------------------------------------------------
// k0: w -> fp16; zero asum.
// ---------------------------------------------------------------------------
__global__ void k0_prep(const float* __restrict__ w) {
    int i = blockIdx.x * 256 + threadIdx.x;
    g_wh[i] = __float2half(w[i]);
    if (i < N_ * K_) g_asum[i] = 0.f;
}

// ---------------------------------------------------------------------------
// B tile stage via cp.async: 64 rows x 64 fp16 from [r*ld + coff]. 4 cp/thread.
// ---------------------------------------------------------------------------
__device__ __forceinline__ void stageB(uint32_t Bd,
                                       const __half* __restrict__ src,
                                       int ld, int coff, int t) {
    int r0 = t >> 3;
    int cc = (t & 7) * 8;
#pragma unroll
    for (int it = 0; it < 4; ++it) {
        int r = it * 16 + r0;
        cpa16(Bd + r * RS + cc * 2, src + (size_t)r * ld + coff + cc);
    }
}

// one ks-slice (k=32 of 64): 6 ldmatrix + 16 HMMA per warp (single term fp16)
__device__ __forceinline__ void mma_ks(int ks, uint32_t A, uint32_t B,
                                       float acc[2][8][4], int w, int lane) {
    int arow = lane & 15;
    int asel = (lane >> 4) * 16;
    int brow = (lane & 7) + ((lane >> 4) << 3);
    int bsel = ((lane >> 3) & 1) * 16;
    int kb = ks * 32;
    uint32_t a[2][4];
#pragma unroll
    for (int mt = 0; mt < 2; ++mt)
        ldmx4(a[mt], A + (w * 32 + mt * 16 + arow) * RS + kb + asel);
    uint32_t b[8][2];
#pragma unroll
    for (int p = 0; p < 4; ++p) {
        uint32_t r[4];
        ldmx4(r, B + (p * 16 + brow) * RS + kb + bsel);
        b[2 * p][0] = r[0]; b[2 * p][1] = r[1];
        b[2 * p + 1][0] = r[2]; b[2 * p + 1][1] = r[3];
    }
#pragma unroll
    for (int mt = 0; mt < 2; ++mt)
#pragma unroll
        for (int nt = 0; nt < 8; ++nt)
            mma16816(acc[mt][nt], a[mt], b[nt]);
}

__device__ __forceinline__ void store_frags(float* Ls, float acc[2][8][4],
                                            int w, int lane) {
#pragma unroll
    for (int mt = 0; mt < 2; ++mt)
#pragma unroll
        for (int nt = 0; nt < 8; ++nt) {
            int r0 = w * 32 + mt * 16 + (lane >> 2);
            int c = nt * 8 + (lane & 3) * 2;
            Ls[r0 * LS_STRIDE + c]           = acc[mt][nt][0];
            Ls[r0 * LS_STRIDE + c + 1]       = acc[mt][nt][1];
            Ls[(r0 + 8) * LS_STRIDE + c]     = acc[mt][nt][2];
            Ls[(r0 + 8) * LS_STRIDE + c + 1] = acc[mt][nt][3];
        }
}

// ---------------------------------------------------------------------------
// g1: logits D[s=128,k=64] over C (8 chunks of 64). fp16 single-term.
// NEW staging: thread owns (s-pair x 32-c) slab: float2 loads + STS.128.
// A-tile layout identical to R10 ([s rows][c], RS=144).
// ---------------------------------------------------------------------------
__global__ void __launch_bounds__(128) g1_logits(const float* __restrict__ x) {
    uint32_t sb = smem_u32(dsm);
    int t = threadIdx.x, w = t >> 5, lane = t & 31;
    int sl = t & 63, hi = t >> 6;
    int sp = 2 * sl;          // s-pair base (0..126)
    int cb = hi * 32;         // c-half offset within 64-chunk
    int n = blockIdx.y, s0 = blockIdx.x * 128;
    const float* xn = x + (size_t)n * C_ * S_ + s0;

    float acc[2][8][4];
#pragma unroll
    for (int i = 0; i < 2; ++i)
#pragma unroll
        for (int j = 0; j < 8; ++j)
#pragma unroll
            for (int q = 0; q < 4; ++q) acc[i][j][q] = 0.f;
    float sq0 = 0.f, sq1 = 0.f;
    float2 xr[32];

#define G1_LOADX(cc0)                                                         \
    _Pragma("unroll")                                                         \
    for (int j = 0; j < 32; ++j)                                              \
        xr[j] = *(const float2*)&xn[(size_t)((cc0) + cb + j) * S_ + sp];

    // convert group g (8 c's = 4 c-pairs) for both s rows: 8 CVT + 2 STS.128
#define G1_CVTG(dst, g) {                                                     \
        uint32_t u0[4], u1[4];                                                \
        _Pragma("unroll")                                                     \
        for (int q = 0; q < 4; ++q) {                                         \
            int cp = (g) * 4 + q;                                             \
            float2 va = xr[2 * cp], vb = xr[2 * cp + 1];                      \
            sq0 += va.x * va.x + vb.x * vb.x;                                 \
            sq1 += va.y * va.y + vb.y * vb.y;                                 \
            u0[q] = cvt2h(va.x, vb.x);                                        \
            u1[q] = cvt2h(va.y, vb.y);                                        \
        }                                                                     \
        sts128((dst) + sp * RS + (cb + (g) * 8) * 2,                          \
               u0[0], u0[1], u0[2], u0[3]);                                   \
        sts128((dst) + (sp + 1) * RS + (cb + (g) * 8) * 2,                    \
               u1[0], u1[1], u1[2], u1[3]); }

    // prologue
    G1_LOADX(0);
    stageB(sb + OB(0), g_wh, C_, 0, t);
    CP_COMMIT();
#pragma unroll
    for (int g = 0; g < 4; ++g) G1_CVTG(sb + OA(0), g);
    G1_LOADX(64);
    stageB(sb + OB(1), g_wh, C_, 64, t);
    CP_COMMIT();
    cp_wait<1>();
    __syncthreads();

    for (int ch = 0; ch < 8; ++ch) {
        int cur = ch & 1, nxt = (ch + 1) & 1;
        bool has_cvt = (ch + 1 < 8);
#pragma unroll
        for (int ks = 0; ks < 4; ++ks) {
            mma_ks(ks, sb + OA(cur), sb + OB(cur), acc, w, lane);
            if (has_cvt) G1_CVTG(sb + OA(nxt), ks);
        }
        if (ch + 2 < 8) { G1_LOADX((ch + 2) * 64); }
        __syncthreads();
        if (ch + 2 < 8) {
            stageB(sb + OB(cur), g_wh, C_, (ch + 2) * 64, t);
            CP_COMMIT();
            cp_wait<1>();
        } else if (ch + 1 < 8) {
            cp_wait<0>();
        }
        if (ch + 1 < 8) __syncthreads();
    }

    // all warps done with tiles before epilogue staging overwrites smem
    __syncthreads();

    float* Ls = (float*)dsm;
    float* ssq = (float*)(dsm + G1_SSQ);
    ssq[hi * 128 + sp]     = sq0;
    ssq[hi * 128 + sp + 1] = sq1;
    store_frags(Ls, acc, w, lane);
    __syncthreads();

    // softmax over k for s = s0+t; logits scaled by invnorm(s)
    float sumsq = ssq[t] + ssq[128 + t];
    float inv = 1.f / fmaxf(sqrtf(sumsq), 1e-12f);
    float m = -1e30f;
#pragma unroll
    for (int k = 0; k < K_; ++k) m = fmaxf(m, Ls[t * LS_STRIDE + k] * inv);
    float sum = 0.f;
#pragma unroll
    for (int k = 0; k < K_; ++k) {
        float e = expf(Ls[t * LS_STRIDE + k] * inv - m);
        Ls[t * LS_STRIDE + k] = e;
        sum += e;
    }
    float rs = 1.f / sum;
#pragma unroll
    for (int k = 0; k < K_; ++k) {
        float a = Ls[t * LS_STRIDE + k] * rs;
        Ls[t * LS_STRIDE + k] = a;                   // unscaled (for asum)
        g_ah[(((size_t)n * K_ + k) << 10) + s0 + t] = __float2half(a * inv);
    }
    __syncthreads();
    if (t < K_) {
        float s = 0.f;
#pragma unroll
        for (int si = 0; si < 128; ++si) s += Ls[si * LS_STRIDE + t];
        atomicAdd(&g_asum[n * K_ + t], s);
    }
}

// ---------------------------------------------------------------------------
// g2: vlad D[c=128,k=64] over S (16 chunks of 64). fp16 single-term.
// NEW staging: float4 loads + STS.64 (R8-style, layout identical to R10).
// ---------------------------------------------------------------------------
__global__ void __launch_bounds__(128) g2_vlad(const float* __restrict__ x) {
    uint32_t sb = smem_u32(dsm);
    int t = threadIdx.x, w = t >> 5, lane = t & 31;
    int n = blockIdx.y, c0 = blockIdx.x * 128;
    const float* xn = x + (size_t)n * C_ * S_;
    const __half* ahn = g_ah + (size_t)n * K_ * S_;

    float acc[2][8][4];
#pragma unroll
    for (int i = 0; i < 2; ++i)
#pragma unroll
        for (int j = 0; j < 8; ++j)
#pragma unroll
            for (int q = 0; q < 4; ++q) acc[i][j][q] = 0.f;
    float4 xr[16];

    // thread owns rows c = it*8 + w*2 + (lane>>4), s-quad (lane&15)*4
#define G2_LOADX(ss0)                                                         \
    _Pragma("unroll")                                                         \
    for (int it = 0; it < 16; ++it)                                           \
        xr[it] = *(const float4*)&xn[(size_t)(c0 + it * 8 + w * 2 + (lane >> 4)) * S_ \
                                     + (ss0) + (lane & 15) * 4];
#define G2_CVTX(dst, it) {                                                    \
        float4 v = xr[it];                                                    \
        sts64((dst) + ((it) * 8 + w * 2 + (lane >> 4)) * RS + (lane & 15) * 8,\
              cvt2h(v.x, v.y), cvt2h(v.z, v.w)); }

    G2_LOADX(0);
    stageB(sb + OB(0), ahn, S_, 0, t);
    CP_COMMIT();
#pragma unroll
    for (int it = 0; it < 16; ++it) G2_CVTX(sb + OA(0), it);
    G2_LOADX(64);
    stageB(sb + OB(1), ahn, S_, 64, t);
    CP_COMMIT();
    cp_wait<1>();
    __syncthreads();

    for (int ch = 0; ch < 16; ++ch) {
        int cur = ch & 1, nxt = (ch + 1) & 1;
        bool has_cvt = (ch + 1 < 16);
#pragma unroll
        for (int ks = 0; ks < 4; ++ks) {
            mma_ks(ks, sb + OA(cur), sb + OB(cur), acc, w, lane);
            if (has_cvt) {
#pragma unroll
                for (int q = 0; q < 4; ++q) G2_CVTX(sb + OA(nxt), ks * 4 + q);
            }
        }
        if (ch + 2 < 16) { G2_LOADX((ch + 2) * 64); }
        __syncthreads();
        if (ch + 2 < 16) {
            stageB(sb + OB(cur), ahn, S_, (ch + 2) * 64, t);
            CP_COMMIT();
            cp_wait<1>();
        } else if (ch + 1 < 16) {
            cp_wait<0>();
        }
        if (ch + 1 < 16) __syncthreads();
    }

    // all warps done with tiles before epilogue staging overwrites smem
    __syncthreads();

    float* Ds = (float*)dsm;
    store_frags(Ds, acc, w, lane);
    __syncthreads();

#pragma unroll 4
    for (int k = 0; k < K_; ++k)
        g_vlad[(((size_t)n * K_ + k) << 9) + c0 + t] = Ds[t * LS_STRIDE + k];
}

// ---------------------------------------------------------------------------
// k4: per-(n,k): val = vlad - asum*centroid; intra-normalize. Global norm is
// EXACTLY 8 (unit rows after intra-norm), so fold 1/8 and write out directly.
// ---------------------------------------------------------------------------
__global__ void k4_intranorm(const float* __restrict__ centroids,
                             float* __restrict__ out) {
    int nk = blockIdx.x;
    int k = nk & 63;
    int t = threadIdx.x;

    float asum = g_asum[nk];
    float4 vv = ((const float4*)(g_vlad + (size_t)nk * C_))[t];
    float4 cc = ((const float4*)(centroids + (size_t)k * C_))[t];
    float4 val;
    val.x = vv.x - asum * cc.x;
    val.y = vv.y - asum * cc.y;
    val.z = vv.z - asum * cc.z;
    val.w = vv.w - asum * cc.w;
    float ss = val.x * val.x + val.y * val.y + val.z * val.z + val.w * val.w;
#pragma unroll
    for (int o = 16; o; o >>= 1) ss += __shfl_xor_sync(0xffffffffu, ss, o);
    __shared__ float red[4];
    if ((t & 31) == 0) red[t >> 5] = ss;
    __syncthreads();
    float total = red[0] + red[1] + red[2] + red[3];

    float invn = 0.125f / fmaxf(sqrtf(total), 1e-12f);
    val.x *= invn; val.y *= invn; val.z *= invn; val.w *= invn;
    ((float4*)(out + (size_t)nk * C_))[t] = val;
}

// ---------------------------------------------------------------------------
extern "C" void kernel_launch(void* const* d_in, const int* in_sizes, int n_in,
                              void* d_out, int out_size) {
    const float* x    = (const float*)d_in[0];
    const float* w    = (const float*)d_in[1];
    const float* cent = (const float*)d_in[2];
    float* out = (float*)d_out;

    cudaFuncSetAttribute(g1_logits, cudaFuncAttributeMaxDynamicSharedMemorySize, SMEM_DYN);
    cudaFuncSetAttribute(g2_vlad,   cudaFuncAttributeMaxDynamicSharedMemorySize, SMEM_DYN);

    k0_prep<<<(K_ * C_) / 256, 256>>>(w);
    g1_logits<<<dim3(S_ / 128, N_), 128, SMEM_DYN>>>(x);
    g2_vlad<<<dim3(C_ / 128, N_), 128, SMEM_DYN>>>(x);
    k4_intranorm<<<N_ * K_, 128>>>(cent, out);
}